// round 1
// baseline (speedup 1.0000x reference)
#include <cuda_runtime.h>
#include <math.h>

// Problem constants
constexpr int kT = 4096;   // tokens
constexpr int kC = 2048;   // channels
constexpr int kH = 16;     // heads
constexpr int kD = 128;    // head dim
constexpr int kNB = 64;    // number of 64-token blocks (kT/64)
constexpr float kScale = 0.08838834764831845f;  // 1/sqrt(128)

// Scratch (device globals — no cudaMalloc allowed)
__device__ float g_q[kT * kC];
__device__ float g_k[kT * kC];
__device__ float g_v[kT * kC];
__device__ float g_ctx[kT * kC];

// ---------------------------------------------------------------------------
// GEMM: C[m,n] = sum_k A[m,k] * B[n,k]   (A: MxK row-major, B: NxK row-major)
// 128x128 tile, K-tile 16, 256 threads, 8x8 accumulators per thread.
// ---------------------------------------------------------------------------
__global__ __launch_bounds__(256) void gemm_abt(const float* __restrict__ A,
                                                const float* __restrict__ B,
                                                float* __restrict__ Cmat,
                                                int M, int N, int K) {
    __shared__ float As[16][128];
    __shared__ float Bs[16][128];

    const int bm = blockIdx.y * 128;
    const int bn = blockIdx.x * 128;
    const int tid = threadIdx.x;
    const int tx = tid & 15;    // 0..15
    const int ty = tid >> 4;    // 0..15

    float acc[8][8];
#pragma unroll
    for (int i = 0; i < 8; i++)
#pragma unroll
        for (int j = 0; j < 8; j++) acc[i][j] = 0.0f;

    const int lrow = tid >> 1;        // 0..127
    const int lk = (tid & 1) * 8;     // 0 or 8
    const float* Aptr = A + (size_t)(bm + lrow) * K + lk;
    const float* Bptr = B + (size_t)(bn + lrow) * K + lk;

    for (int k0 = 0; k0 < K; k0 += 16) {
        float4 a0 = *(const float4*)(Aptr + k0);
        float4 a1 = *(const float4*)(Aptr + k0 + 4);
        float4 b0 = *(const float4*)(Bptr + k0);
        float4 b1 = *(const float4*)(Bptr + k0 + 4);
        __syncthreads();
        As[lk + 0][lrow] = a0.x; As[lk + 1][lrow] = a0.y;
        As[lk + 2][lrow] = a0.z; As[lk + 3][lrow] = a0.w;
        As[lk + 4][lrow] = a1.x; As[lk + 5][lrow] = a1.y;
        As[lk + 6][lrow] = a1.z; As[lk + 7][lrow] = a1.w;
        Bs[lk + 0][lrow] = b0.x; Bs[lk + 1][lrow] = b0.y;
        Bs[lk + 2][lrow] = b0.z; Bs[lk + 3][lrow] = b0.w;
        Bs[lk + 4][lrow] = b1.x; Bs[lk + 5][lrow] = b1.y;
        Bs[lk + 6][lrow] = b1.z; Bs[lk + 7][lrow] = b1.w;
        __syncthreads();

#pragma unroll
        for (int kk = 0; kk < 16; kk++) {
            float ar[8], br[8];
            *(float4*)(ar)     = *(const float4*)&As[kk][ty * 8];
            *(float4*)(ar + 4) = *(const float4*)&As[kk][ty * 8 + 4];
            // column split: cols [tx*4, tx*4+4) and [64 + tx*4, 64 + tx*4+4)
            *(float4*)(br)     = *(const float4*)&Bs[kk][tx * 4];
            *(float4*)(br + 4) = *(const float4*)&Bs[kk][64 + tx * 4];
#pragma unroll
            for (int i = 0; i < 8; i++)
#pragma unroll
                for (int j = 0; j < 8; j++) acc[i][j] += ar[i] * br[j];
        }
    }

#pragma unroll
    for (int i = 0; i < 8; i++) {
        const int row = bm + ty * 8 + i;
        float4 c0 = make_float4(acc[i][0], acc[i][1], acc[i][2], acc[i][3]);
        float4 c1 = make_float4(acc[i][4], acc[i][5], acc[i][6], acc[i][7]);
        *(float4*)&Cmat[(size_t)row * N + bn + tx * 4] = c0;
        *(float4*)&Cmat[(size_t)row * N + bn + 64 + tx * 4] = c1;
    }
}

// ---------------------------------------------------------------------------
// RoPE applied in-place to Q and K laid out as [T, H*D].
// For head h, pair i in [0,64): angle = t * 10000^(-i/64)
//   out[i]    = x1*cos - x2*sin
//   out[i+64] = x2*cos + x1*sin
// ---------------------------------------------------------------------------
__global__ void rope_kernel(float* __restrict__ Q, float* __restrict__ K) {
    const int t = blockIdx.x;
    const float ft = (float)t;
    for (int p = threadIdx.x; p < kH * 64; p += blockDim.x) {
        const int h = p >> 6;
        const int i = p & 63;
        // inv_freq = exp(-i * ln(10000)/64)
        const float inv = __expf(-(float)i * 0.14391157f);
        const float ang = ft * inv;
        float s, c;
        sincosf(ang, &s, &c);
        const size_t base = (size_t)t * kC + h * kD;
        {
            float x1 = Q[base + i], x2 = Q[base + 64 + i];
            Q[base + i]      = x1 * c - x2 * s;
            Q[base + 64 + i] = x2 * c + x1 * s;
        }
        {
            float x1 = K[base + i], x2 = K[base + 64 + i];
            K[base + i]      = x1 * c - x2 * s;
            K[base + 64 + i] = x2 * c + x1 * s;
        }
    }
}

// ---------------------------------------------------------------------------
// Block-sparse flash attention. One CTA per (q-block, head).
// Block mask at 64-token granularity (exact):
//   allowed(kb) = kb <= qb && ((qb-kb) <= 16 || kb < 2 || (kb & 3) == 0)
// 256 threads: thread = 4*row + quarter. Each thread computes 16 score cols
// and 32 output dims for its row. Online softmax with 4-lane shfl reductions.
// ---------------------------------------------------------------------------
constexpr int QS_LD  = 132;  // padded leading dim for Q tile [64][132]
constexpr int KST_LD = 68;   // K stored d-major: [128][68]
constexpr int PS_LD  = 65;   // P tile [64][65]
constexpr int ATTN_SMEM_FLOATS = 64 * QS_LD + 128 * KST_LD + 64 * 128 + 64 * PS_LD;
constexpr int ATTN_SMEM_BYTES  = ATTN_SMEM_FLOATS * 4;  // 118,016 B

__global__ __launch_bounds__(256) void attn_kernel(const float* __restrict__ Q,
                                                   const float* __restrict__ K,
                                                   const float* __restrict__ V,
                                                   float* __restrict__ Ctx) {
    extern __shared__ float sm[];
    float* Qs  = sm;                       // [64][QS_LD]
    float* Kst = Qs + 64 * QS_LD;          // [128][KST_LD]  (d-major)
    float* Vs  = Kst + 128 * KST_LD;       // [64][128]
    float* Ps  = Vs + 64 * 128;            // [64][PS_LD]

    const int qb = blockIdx.x;
    const int h  = blockIdx.y;
    const int tid = threadIdx.x;
    const int r  = tid >> 2;   // row 0..63
    const int qd = tid & 3;    // quarter 0..3

    // Load Q tile, pre-scaled
    for (int idx = tid * 4; idx < 64 * 128; idx += 1024) {
        const int rr = idx >> 7;
        const int dd = idx & 127;
        float4 qv = *(const float4*)&Q[(size_t)(qb * 64 + rr) * kC + h * kD + dd];
        qv.x *= kScale; qv.y *= kScale; qv.z *= kScale; qv.w *= kScale;
        *(float4*)&Qs[rr * QS_LD + dd] = qv;
    }

    float m = -INFINITY, l = 0.0f;
    float o[32];
#pragma unroll
    for (int j = 0; j < 32; j++) o[j] = 0.0f;

    __syncthreads();

    for (int kb = 0; kb <= qb; kb++) {
        const int dist = qb - kb;
        if (!((dist <= 16) || (kb < 2) || ((kb & 3) == 0))) continue;

        __syncthreads();  // previous iteration's PV reads done
        // Load K (d-major) and V tiles
        for (int idx = tid * 4; idx < 64 * 128; idx += 1024) {
            const int rr = idx >> 7;
            const int dd = idx & 127;
            const size_t gbase = (size_t)(kb * 64 + rr) * kC + h * kD + dd;
            const float4 kv = *(const float4*)&K[gbase];
            Kst[(dd + 0) * KST_LD + rr] = kv.x;
            Kst[(dd + 1) * KST_LD + rr] = kv.y;
            Kst[(dd + 2) * KST_LD + rr] = kv.z;
            Kst[(dd + 3) * KST_LD + rr] = kv.w;
            *(float4*)&Vs[rr * 128 + dd] = *(const float4*)&V[gbase];
        }
        __syncthreads();

        // Scores: this thread owns cols [qd*16, qd*16+16)
        float s[16];
#pragma unroll
        for (int j = 0; j < 16; j++) s[j] = 0.0f;
        const float* kcol = Kst + qd * 16;
        const float* qrow = Qs + r * QS_LD;
#pragma unroll 4
        for (int d = 0; d < 128; d++) {
            const float qv = qrow[d];
            const float4 k0 = *(const float4*)(kcol + d * KST_LD);
            const float4 k1 = *(const float4*)(kcol + d * KST_LD + 4);
            const float4 k2 = *(const float4*)(kcol + d * KST_LD + 8);
            const float4 k3 = *(const float4*)(kcol + d * KST_LD + 12);
            s[0]  += qv * k0.x; s[1]  += qv * k0.y; s[2]  += qv * k0.z; s[3]  += qv * k0.w;
            s[4]  += qv * k1.x; s[5]  += qv * k1.y; s[6]  += qv * k1.z; s[7]  += qv * k1.w;
            s[8]  += qv * k2.x; s[9]  += qv * k2.y; s[10] += qv * k2.z; s[11] += qv * k2.w;
            s[12] += qv * k3.x; s[13] += qv * k3.y; s[14] += qv * k3.z; s[15] += qv * k3.w;
        }

        // Online softmax (row reduction across the 4 lanes that share row r)
        float lm = s[0];
#pragma unroll
        for (int j = 1; j < 16; j++) lm = fmaxf(lm, s[j]);
        lm = fmaxf(lm, __shfl_xor_sync(0xFFFFFFFFu, lm, 1));
        lm = fmaxf(lm, __shfl_xor_sync(0xFFFFFFFFu, lm, 2));
        const float mnew = fmaxf(m, lm);
        const float corr = __expf(m - mnew);   // exp(-inf)=0 on first visit
        float rs = 0.0f;
#pragma unroll
        for (int j = 0; j < 16; j++) {
            const float p = __expf(s[j] - mnew);
            Ps[r * PS_LD + qd * 16 + j] = p;
            rs += p;
        }
        rs += __shfl_xor_sync(0xFFFFFFFFu, rs, 1);
        rs += __shfl_xor_sync(0xFFFFFFFFu, rs, 2);
        l = l * corr + rs;
        m = mnew;
#pragma unroll
        for (int j = 0; j < 32; j++) o[j] *= corr;
        __syncthreads();

        // O += P @ V  (this thread owns dims [qd*32, qd*32+32) of row r)
        const float* vcol = Vs + qd * 32;
        const float* prow = Ps + r * PS_LD;
#pragma unroll 4
        for (int c = 0; c < 64; c++) {
            const float p = prow[c];
#pragma unroll
            for (int j = 0; j < 8; j++) {
                const float4 v = *(const float4*)(vcol + c * 128 + j * 4);
                o[j * 4 + 0] += p * v.x;
                o[j * 4 + 1] += p * v.y;
                o[j * 4 + 2] += p * v.z;
                o[j * 4 + 3] += p * v.w;
            }
        }
    }

    const float invl = 1.0f / l;
    const size_t obase = (size_t)(qb * 64 + r) * kC + h * kD + qd * 32;
#pragma unroll
    for (int j = 0; j < 8; j++) {
        float4 ov = make_float4(o[j * 4 + 0] * invl, o[j * 4 + 1] * invl,
                                o[j * 4 + 2] * invl, o[j * 4 + 3] * invl);
        *(float4*)&Ctx[obase + j * 4] = ov;
    }
}

// ---------------------------------------------------------------------------
extern "C" void kernel_launch(void* const* d_in, const int* in_sizes, int n_in,
                              void* d_out, int out_size) {
    const float* x  = (const float*)d_in[0];
    const float* wq = (const float*)d_in[1];
    const float* wk = (const float*)d_in[2];
    const float* wv = (const float*)d_in[3];
    const float* wo = (const float*)d_in[4];
    float* out = (float*)d_out;

    float *qp, *kp, *vp, *cp;
    cudaGetSymbolAddress((void**)&qp, g_q);
    cudaGetSymbolAddress((void**)&kp, g_k);
    cudaGetSymbolAddress((void**)&vp, g_v);
    cudaGetSymbolAddress((void**)&cp, g_ctx);

    const dim3 ggrid(kC / 128, kT / 128);

    gemm_abt<<<ggrid, 256>>>(x, wq, qp, kT, kC, kC);
    gemm_abt<<<ggrid, 256>>>(x, wk, kp, kT, kC, kC);
    gemm_abt<<<ggrid, 256>>>(x, wv, vp, kT, kC, kC);

    rope_kernel<<<kT, 256>>>(qp, kp);

    cudaFuncSetAttribute(attn_kernel, cudaFuncAttributeMaxDynamicSharedMemorySize,
                         ATTN_SMEM_BYTES);
    attn_kernel<<<dim3(kNB, kH), 256, ATTN_SMEM_BYTES>>>(qp, kp, vp, cp);

    gemm_abt<<<ggrid, 256>>>(cp, wo, out, kT, kC, kC);
}

// round 3
// speedup vs baseline: 3.6318x; 3.6318x over previous
#include <cuda_runtime.h>
#include <math.h>
#include <stdint.h>

// Problem constants
constexpr int kT = 4096;
constexpr int kC = 2048;
constexpr int kH = 16;
constexpr int kD = 128;
constexpr int kNB = 64;
constexpr float kScale = 0.08838834764831845f;

// Scratch (device globals — no cudaMalloc allowed)
__device__ float g_q[kT * kC];
__device__ float g_k[kT * kC];
__device__ float g_v[kT * kC];
__device__ float g_ctx[kT * kC];
__device__ float g_xr[kT * kC];          // tf32-rounded x
__device__ float g_wr[4 * kC * kC];      // tf32-rounded wq,wk,wv,wo

// ---------------------------------------------------------------------------
__device__ __forceinline__ uint32_t smem_u32(const void* p) {
    uint32_t a;
    asm("{ .reg .u64 t; cvta.to.shared.u64 t, %1; cvt.u32.u64 %0, t; }"
        : "=r"(a) : "l"(p));
    return a;
}

__device__ __forceinline__ void cp_async16(uint32_t saddr, const void* gaddr) {
    asm volatile("cp.async.cg.shared.global [%0], [%1], 16;"
                 :: "r"(saddr), "l"(gaddr));
}
#define CP_COMMIT() asm volatile("cp.async.commit_group;" ::: "memory")

__device__ __forceinline__ float round_tf32(float x) {
    uint32_t u;
    asm("cvt.rna.tf32.f32 %0, %1;" : "=r"(u) : "f"(x));
    return __uint_as_float(u);
}

// mma.sync m16n8k8 tf32: D(16x8 f32) += A(16x8) * B(8x8)
__device__ __forceinline__ void mma_tf32(float* d, const uint32_t* a,
                                         const uint32_t* b) {
    asm volatile(
        "mma.sync.aligned.m16n8k8.row.col.f32.tf32.tf32.f32 "
        "{%0,%1,%2,%3}, {%4,%5,%6,%7}, {%8,%9}, {%0,%1,%2,%3};"
        : "+f"(d[0]), "+f"(d[1]), "+f"(d[2]), "+f"(d[3])
        : "r"(a[0]), "r"(a[1]), "r"(a[2]), "r"(a[3]), "r"(b[0]), "r"(b[1]));
}

// ---------------------------------------------------------------------------
// Elementwise round-to-nearest tf32 (pre-pass for GEMM inputs)
// ---------------------------------------------------------------------------
__global__ void round_kernel(const float* __restrict__ src,
                             float* __restrict__ dst, int n4) {
    int i = blockIdx.x * blockDim.x + threadIdx.x;
    if (i < n4) {
        float4 v = ((const float4*)src)[i];
        v.x = round_tf32(v.x); v.y = round_tf32(v.y);
        v.z = round_tf32(v.z); v.w = round_tf32(v.w);
        ((float4*)dst)[i] = v;
    }
}

// ---------------------------------------------------------------------------
// TF32 tensor-core GEMM: C[m,n] = sum_k A[m,k] * B[n,k]
// CTA tile 128x128x32, 8 warps (warp tile 32x64), cp.async double buffer.
// A, B assumed already tf32-rounded. Smem pad 36 floats (conflict-free LDS,
// 144B rows keep 16B cp.async alignment).
// ---------------------------------------------------------------------------
constexpr int GLD = 36;                       // smem leading dim (floats)
constexpr int GSTAGE_FLOATS = 2 * 128 * GLD;  // A + B per stage = 9216
constexpr int GEMM_SMEM_BYTES = 2 * GSTAGE_FLOATS * 4;  // 73728

__global__ __launch_bounds__(256, 2) void gemm_tc(const float* __restrict__ A,
                                                  const float* __restrict__ B,
                                                  float* __restrict__ C,
                                                  int M, int N, int K) {
    extern __shared__ float smf[];
    const uint32_t sb = smem_u32(smf);
    const int tid = threadIdx.x;
    const int lane = tid & 31;
    const int wid = tid >> 5;
    const int warp_m = wid & 3;   // 0..3 -> m rows warp_m*32
    const int warp_n = wid >> 2;  // 0..1 -> n cols warp_n*64
    const int bm = blockIdx.y * 128;
    const int bn = blockIdx.x * 128;

    const int lrow = tid >> 3;          // 0..31 over 4 iters -> 0..127
    const int lc4 = (tid & 7) << 2;     // 0,4,...,28

    float d[2][8][4];
#pragma unroll
    for (int mi = 0; mi < 2; mi++)
#pragma unroll
        for (int ni = 0; ni < 8; ni++)
#pragma unroll
            for (int j = 0; j < 4; j++) d[mi][ni][j] = 0.0f;

    const int nStages = K / 32;

    // prefetch helper (macro-ish via lambda)
    auto prefetch = [&](int s) {
        const int buf = s & 1;
        const uint32_t ab = sb + buf * GSTAGE_FLOATS * 4;
        const uint32_t bb = ab + 128 * GLD * 4;
        const int k0 = s * 32;
#pragma unroll
        for (int j = 0; j < 4; j++) {
            const int row = lrow + j * 32;
            const uint32_t soff = (uint32_t)(row * GLD + lc4) * 4;
            cp_async16(ab + soff, &A[(size_t)(bm + row) * K + k0 + lc4]);
            cp_async16(bb + soff, &B[(size_t)(bn + row) * K + k0 + lc4]);
        }
        CP_COMMIT();
    };

    prefetch(0);

    for (int s = 0; s < nStages; s++) {
        if (s + 1 < nStages) {
            prefetch(s + 1);
            asm volatile("cp.async.wait_group 1;" ::: "memory");
        } else {
            asm volatile("cp.async.wait_group 0;" ::: "memory");
        }
        __syncthreads();

        const int buf = s & 1;
        const uint32_t* As = (const uint32_t*)(smf + buf * GSTAGE_FLOATS);
        const uint32_t* Bs = As + 128 * GLD;

#pragma unroll
        for (int kk = 0; kk < 4; kk++) {
            uint32_t a[2][4];
#pragma unroll
            for (int mi = 0; mi < 2; mi++) {
                const int r0 = warp_m * 32 + mi * 16 + (lane >> 2);
                const int c0 = kk * 8 + (lane & 3);
                a[mi][0] = As[r0 * GLD + c0];
                a[mi][1] = As[(r0 + 8) * GLD + c0];
                a[mi][2] = As[r0 * GLD + c0 + 4];
                a[mi][3] = As[(r0 + 8) * GLD + c0 + 4];
            }
            uint32_t b[8][2];
#pragma unroll
            for (int ni = 0; ni < 8; ni++) {
                const int n0 = warp_n * 64 + ni * 8 + (lane >> 2);
                const int c0 = kk * 8 + (lane & 3);
                b[ni][0] = Bs[n0 * GLD + c0];
                b[ni][1] = Bs[n0 * GLD + c0 + 4];
            }
#pragma unroll
            for (int mi = 0; mi < 2; mi++)
#pragma unroll
                for (int ni = 0; ni < 8; ni++)
                    mma_tf32(d[mi][ni], a[mi], b[ni]);
        }
        __syncthreads();
    }

    // Epilogue
#pragma unroll
    for (int mi = 0; mi < 2; mi++) {
        const int row = bm + warp_m * 32 + mi * 16 + (lane >> 2);
#pragma unroll
        for (int ni = 0; ni < 8; ni++) {
            const int col = bn + warp_n * 64 + ni * 8 + ((lane & 3) << 1);
            *(float2*)&C[(size_t)row * N + col] = make_float2(d[mi][ni][0], d[mi][ni][1]);
            *(float2*)&C[(size_t)(row + 8) * N + col] = make_float2(d[mi][ni][2], d[mi][ni][3]);
        }
    }
}

// ---------------------------------------------------------------------------
// RoPE in-place on Q and K laid out [T, H*D].
// ---------------------------------------------------------------------------
__global__ void rope_kernel(float* __restrict__ Q, float* __restrict__ K) {
    const int t = blockIdx.x;
    const float ft = (float)t;
    for (int p = threadIdx.x; p < kH * 64; p += blockDim.x) {
        const int h = p >> 6;
        const int i = p & 63;
        const float inv = __expf(-(float)i * 0.14391157f);
        float s, c;
        sincosf(ft * inv, &s, &c);
        const size_t base = (size_t)t * kC + h * kD;
        {
            float x1 = Q[base + i], x2 = Q[base + 64 + i];
            Q[base + i]      = x1 * c - x2 * s;
            Q[base + 64 + i] = x2 * c + x1 * s;
        }
        {
            float x1 = K[base + i], x2 = K[base + 64 + i];
            K[base + i]      = x1 * c - x2 * s;
            K[base + 64 + i] = x2 * c + x1 * s;
        }
    }
}

// ---------------------------------------------------------------------------
// Block-sparse flash attention. One CTA per (q-block, head).
// allowed(kb) = kb <= qb && ((qb-kb) <= 16 || kb < 2 || (kb & 3) == 0)
// 256 threads as 16x16 grid: tr owns rows tr*4..+3, tc owns score cols
// tc*4..+3 and output dims tc*8..+7. K/V share one smem buffer.
// Output rounded to tf32 (RN) so the final GEMM stays unbiased.
// ---------------------------------------------------------------------------
constexpr int AKV_LD = 72;
constexpr int APS_LD = 68;
constexpr int ATTN_SMEM_FLOATS = 64 * 128 + 128 * AKV_LD + 64 * APS_LD;
constexpr int ATTN_SMEM_BYTES = ATTN_SMEM_FLOATS * 4;   // 87,040 B

__global__ __launch_bounds__(256, 2) void attn_kernel(const float* __restrict__ Q,
                                                      const float* __restrict__ K,
                                                      const float* __restrict__ V,
                                                      float* __restrict__ Ctx) {
    extern __shared__ float sm[];
    float* Qs = sm;                        // [64][128]
    float* KV = sm + 64 * 128;             // K: [128][72] d-major; V: [64][128]
    float* Ps = KV + 128 * AKV_LD;         // [64][68]

    const int qb = blockIdx.x;
    const int h = blockIdx.y;
    const int tid = threadIdx.x;
    const int tr = tid >> 4;
    const int tc = tid & 15;

    for (int idx = tid * 4; idx < 64 * 128; idx += 1024) {
        const int rr = idx >> 7;
        const int dd = idx & 127;
        float4 qv = *(const float4*)&Q[(size_t)(qb * 64 + rr) * kC + h * kD + dd];
        qv.x *= kScale; qv.y *= kScale; qv.z *= kScale; qv.w *= kScale;
        *(float4*)&Qs[rr * 128 + dd] = qv;
    }

    float m[4], l[4], o[4][8];
#pragma unroll
    for (int i = 0; i < 4; i++) {
        m[i] = -INFINITY;
        l[i] = 0.0f;
#pragma unroll
        for (int j = 0; j < 8; j++) o[i][j] = 0.0f;
    }

    __syncthreads();

    for (int kb = 0; kb <= qb; kb++) {
        const int dist = qb - kb;
        if (!((dist <= 16) || (kb < 2) || ((kb & 3) == 0))) continue;

        __syncthreads();
        for (int idx = tid * 4; idx < 64 * 128; idx += 1024) {
            const int rr = idx >> 7;
            const int dd = idx & 127;
            const float4 kv4 = *(const float4*)&K[(size_t)(kb * 64 + rr) * kC + h * kD + dd];
            KV[(dd + 0) * AKV_LD + rr] = kv4.x;
            KV[(dd + 1) * AKV_LD + rr] = kv4.y;
            KV[(dd + 2) * AKV_LD + rr] = kv4.z;
            KV[(dd + 3) * AKV_LD + rr] = kv4.w;
        }
        __syncthreads();

        float s[4][4];
#pragma unroll
        for (int i = 0; i < 4; i++)
#pragma unroll
            for (int j = 0; j < 4; j++) s[i][j] = 0.0f;

        const float* kbase = KV + tc * 4;
        const float* q0p = Qs + (tr * 4 + 0) * 128;
        const float* q1p = Qs + (tr * 4 + 1) * 128;
        const float* q2p = Qs + (tr * 4 + 2) * 128;
        const float* q3p = Qs + (tr * 4 + 3) * 128;
#pragma unroll 4
        for (int d = 0; d < 128; d++) {
            const float4 kv = *(const float4*)(kbase + d * AKV_LD);
            const float q0 = q0p[d], q1 = q1p[d], q2 = q2p[d], q3 = q3p[d];
            s[0][0] += q0 * kv.x; s[0][1] += q0 * kv.y; s[0][2] += q0 * kv.z; s[0][3] += q0 * kv.w;
            s[1][0] += q1 * kv.x; s[1][1] += q1 * kv.y; s[1][2] += q1 * kv.z; s[1][3] += q1 * kv.w;
            s[2][0] += q2 * kv.x; s[2][1] += q2 * kv.y; s[2][2] += q2 * kv.z; s[2][3] += q2 * kv.w;
            s[3][0] += q3 * kv.x; s[3][1] += q3 * kv.y; s[3][2] += q3 * kv.z; s[3][3] += q3 * kv.w;
        }

#pragma unroll
        for (int i = 0; i < 4; i++) {
            float lm = fmaxf(fmaxf(s[i][0], s[i][1]), fmaxf(s[i][2], s[i][3]));
            lm = fmaxf(lm, __shfl_xor_sync(0xFFFFFFFFu, lm, 1));
            lm = fmaxf(lm, __shfl_xor_sync(0xFFFFFFFFu, lm, 2));
            lm = fmaxf(lm, __shfl_xor_sync(0xFFFFFFFFu, lm, 4));
            lm = fmaxf(lm, __shfl_xor_sync(0xFFFFFFFFu, lm, 8));
            const float mnew = fmaxf(m[i], lm);
            const float corr = __expf(m[i] - mnew);
            float4 p;
            p.x = __expf(s[i][0] - mnew);
            p.y = __expf(s[i][1] - mnew);
            p.z = __expf(s[i][2] - mnew);
            p.w = __expf(s[i][3] - mnew);
            float rs = (p.x + p.y) + (p.z + p.w);
            rs += __shfl_xor_sync(0xFFFFFFFFu, rs, 1);
            rs += __shfl_xor_sync(0xFFFFFFFFu, rs, 2);
            rs += __shfl_xor_sync(0xFFFFFFFFu, rs, 4);
            rs += __shfl_xor_sync(0xFFFFFFFFu, rs, 8);
            l[i] = l[i] * corr + rs;
            m[i] = mnew;
#pragma unroll
            for (int j = 0; j < 8; j++) o[i][j] *= corr;
            *(float4*)&Ps[(tr * 4 + i) * APS_LD + tc * 4] = p;
        }
        __syncthreads();

        for (int idx = tid * 4; idx < 64 * 128; idx += 1024) {
            const int rr = idx >> 7;
            const int dd = idx & 127;
            *(float4*)&KV[rr * 128 + dd] =
                *(const float4*)&V[(size_t)(kb * 64 + rr) * kC + h * kD + dd];
        }
        __syncthreads();

        const float* vbase = KV + tc * 8;
        const float* p0p = Ps + (tr * 4 + 0) * APS_LD;
        const float* p1p = Ps + (tr * 4 + 1) * APS_LD;
        const float* p2p = Ps + (tr * 4 + 2) * APS_LD;
        const float* p3p = Ps + (tr * 4 + 3) * APS_LD;
#pragma unroll 4
        for (int c = 0; c < 64; c++) {
            const float4 v0 = *(const float4*)(vbase + c * 128);
            const float4 v1 = *(const float4*)(vbase + c * 128 + 4);
            const float p0 = p0p[c], p1 = p1p[c], p2 = p2p[c], p3 = p3p[c];
            o[0][0] += p0 * v0.x; o[0][1] += p0 * v0.y; o[0][2] += p0 * v0.z; o[0][3] += p0 * v0.w;
            o[0][4] += p0 * v1.x; o[0][5] += p0 * v1.y; o[0][6] += p0 * v1.z; o[0][7] += p0 * v1.w;
            o[1][0] += p1 * v0.x; o[1][1] += p1 * v0.y; o[1][2] += p1 * v0.z; o[1][3] += p1 * v0.w;
            o[1][4] += p1 * v1.x; o[1][5] += p1 * v1.y; o[1][6] += p1 * v1.z; o[1][7] += p1 * v1.w;
            o[2][0] += p2 * v0.x; o[2][1] += p2 * v0.y; o[2][2] += p2 * v0.z; o[2][3] += p2 * v0.w;
            o[2][4] += p2 * v1.x; o[2][5] += p2 * v1.y; o[2][6] += p2 * v1.z; o[2][7] += p2 * v1.w;
            o[3][0] += p3 * v0.x; o[3][1] += p3 * v0.y; o[3][2] += p3 * v0.z; o[3][3] += p3 * v0.w;
            o[3][4] += p3 * v1.x; o[3][5] += p3 * v1.y; o[3][6] += p3 * v1.z; o[3][7] += p3 * v1.w;
        }
    }

#pragma unroll
    for (int i = 0; i < 4; i++) {
        const float invl = 1.0f / l[i];
        const size_t obase = (size_t)(qb * 64 + tr * 4 + i) * kC + h * kD + tc * 8;
        float4 a = make_float4(round_tf32(o[i][0] * invl), round_tf32(o[i][1] * invl),
                               round_tf32(o[i][2] * invl), round_tf32(o[i][3] * invl));
        float4 b = make_float4(round_tf32(o[i][4] * invl), round_tf32(o[i][5] * invl),
                               round_tf32(o[i][6] * invl), round_tf32(o[i][7] * invl));
        *(float4*)&Ctx[obase] = a;
        *(float4*)&Ctx[obase + 4] = b;
    }
}

// ---------------------------------------------------------------------------
extern "C" void kernel_launch(void* const* d_in, const int* in_sizes, int n_in,
                              void* d_out, int out_size) {
    const float* x  = (const float*)d_in[0];
    const float* wq = (const float*)d_in[1];
    const float* wk = (const float*)d_in[2];
    const float* wv = (const float*)d_in[3];
    const float* wo = (const float*)d_in[4];
    float* out = (float*)d_out;

    float *qp, *kp, *vp, *cp, *xr, *wr;
    cudaGetSymbolAddress((void**)&qp, g_q);
    cudaGetSymbolAddress((void**)&kp, g_k);
    cudaGetSymbolAddress((void**)&vp, g_v);
    cudaGetSymbolAddress((void**)&cp, g_ctx);
    cudaGetSymbolAddress((void**)&xr, g_xr);
    cudaGetSymbolAddress((void**)&wr, g_wr);

    cudaFuncSetAttribute(gemm_tc, cudaFuncAttributeMaxDynamicSharedMemorySize,
                         GEMM_SMEM_BYTES);
    cudaFuncSetAttribute(attn_kernel, cudaFuncAttributeMaxDynamicSharedMemorySize,
                         ATTN_SMEM_BYTES);

    const int CC = kC * kC;
    round_kernel<<<(kT * kC / 4 + 255) / 256, 256>>>(x, xr, kT * kC / 4);
    round_kernel<<<(CC / 4 + 255) / 256, 256>>>(wq, wr + 0 * CC, CC / 4);
    round_kernel<<<(CC / 4 + 255) / 256, 256>>>(wk, wr + 1 * CC, CC / 4);
    round_kernel<<<(CC / 4 + 255) / 256, 256>>>(wv, wr + 2 * CC, CC / 4);
    round_kernel<<<(CC / 4 + 255) / 256, 256>>>(wo, wr + 3 * CC, CC / 4);

    const dim3 ggrid(kC / 128, kT / 128);
    gemm_tc<<<ggrid, 256, GEMM_SMEM_BYTES>>>(xr, wr + 0 * CC, qp, kT, kC, kC);
    gemm_tc<<<ggrid, 256, GEMM_SMEM_BYTES>>>(xr, wr + 1 * CC, kp, kT, kC, kC);
    gemm_tc<<<ggrid, 256, GEMM_SMEM_BYTES>>>(xr, wr + 2 * CC, vp, kT, kC, kC);

    rope_kernel<<<kT, 256>>>(qp, kp);

    attn_kernel<<<dim3(kNB, kH), 256, ATTN_SMEM_BYTES>>>(qp, kp, vp, cp);

    gemm_tc<<<ggrid, 256, GEMM_SMEM_BYTES>>>(cp, wr + 3 * CC, out, kT, kC, kC);
}

// round 4
// speedup vs baseline: 7.2621x; 1.9996x over previous
#include <cuda_runtime.h>
#include <math.h>
#include <stdint.h>

// Problem constants
constexpr int kT = 4096;
constexpr int kC = 2048;
constexpr int kH = 16;
constexpr int kD = 128;
constexpr int kNB = 64;
constexpr float kScale = 0.08838834764831845f;

// Scratch (device globals — no cudaMalloc allowed)
__device__ float g_q[kT * kC];
__device__ float g_k[kT * kC];
__device__ float g_v[kT * kC];
__device__ float g_ctx[kT * kC];
__device__ float g_xr[kT * kC];          // tf32-rounded x
__device__ float g_wr[4 * kC * kC];      // tf32-rounded wq,wk,wv,wo

// ---------------------------------------------------------------------------
__device__ __forceinline__ uint32_t smem_u32(const void* p) {
    uint32_t a;
    asm("{ .reg .u64 t; cvta.to.shared.u64 t, %1; cvt.u32.u64 %0, t; }"
        : "=r"(a) : "l"(p));
    return a;
}

__device__ __forceinline__ void cp_async16(uint32_t saddr, const void* gaddr) {
    asm volatile("cp.async.cg.shared.global [%0], [%1], 16;"
                 :: "r"(saddr), "l"(gaddr));
}
#define CP_COMMIT() asm volatile("cp.async.commit_group;" ::: "memory")

__device__ __forceinline__ float round_tf32(float x) {
    uint32_t u;
    asm("cvt.rna.tf32.f32 %0, %1;" : "=r"(u) : "f"(x));
    return __uint_as_float(u);
}

// mma.sync m16n8k8 tf32: D(16x8 f32) += A(16x8) * B(8x8)
__device__ __forceinline__ void mma_tf32(float* d, const uint32_t* a,
                                         const uint32_t* b) {
    asm volatile(
        "mma.sync.aligned.m16n8k8.row.col.f32.tf32.tf32.f32 "
        "{%0,%1,%2,%3}, {%4,%5,%6,%7}, {%8,%9}, {%0,%1,%2,%3};"
        : "+f"(d[0]), "+f"(d[1]), "+f"(d[2]), "+f"(d[3])
        : "r"(a[0]), "r"(a[1]), "r"(a[2]), "r"(a[3]), "r"(b[0]), "r"(b[1]));
}

// ---------------------------------------------------------------------------
// Elementwise round-to-nearest tf32 (pre-pass for GEMM inputs)
// ---------------------------------------------------------------------------
__global__ void round_kernel(const float* __restrict__ src,
                             float* __restrict__ dst, int n4) {
    int i = blockIdx.x * blockDim.x + threadIdx.x;
    if (i < n4) {
        float4 v = ((const float4*)src)[i];
        v.x = round_tf32(v.x); v.y = round_tf32(v.y);
        v.z = round_tf32(v.z); v.w = round_tf32(v.w);
        ((float4*)dst)[i] = v;
    }
}

// ---------------------------------------------------------------------------
// TF32 tensor-core GEMM: C[m,n] = sum_k A[m,k] * B[n,k]
// CTA tile 128x128x32, 8 warps (warp tile 32x64), cp.async double buffer.
// ---------------------------------------------------------------------------
constexpr int GLD = 36;
constexpr int GSTAGE_FLOATS = 2 * 128 * GLD;
constexpr int GEMM_SMEM_BYTES = 2 * GSTAGE_FLOATS * 4;  // 73728

__global__ __launch_bounds__(256, 2) void gemm_tc(const float* __restrict__ A,
                                                  const float* __restrict__ B,
                                                  float* __restrict__ C,
                                                  int M, int N, int K) {
    extern __shared__ float smf[];
    const uint32_t sb = smem_u32(smf);
    const int tid = threadIdx.x;
    const int lane = tid & 31;
    const int wid = tid >> 5;
    const int warp_m = wid & 3;
    const int warp_n = wid >> 2;
    const int bm = blockIdx.y * 128;
    const int bn = blockIdx.x * 128;

    const int lrow = tid >> 3;
    const int lc4 = (tid & 7) << 2;

    float d[2][8][4];
#pragma unroll
    for (int mi = 0; mi < 2; mi++)
#pragma unroll
        for (int ni = 0; ni < 8; ni++)
#pragma unroll
            for (int j = 0; j < 4; j++) d[mi][ni][j] = 0.0f;

    const int nStages = K / 32;

    auto prefetch = [&](int s) {
        const int buf = s & 1;
        const uint32_t ab = sb + buf * GSTAGE_FLOATS * 4;
        const uint32_t bb = ab + 128 * GLD * 4;
        const int k0 = s * 32;
#pragma unroll
        for (int j = 0; j < 4; j++) {
            const int row = lrow + j * 32;
            const uint32_t soff = (uint32_t)(row * GLD + lc4) * 4;
            cp_async16(ab + soff, &A[(size_t)(bm + row) * K + k0 + lc4]);
            cp_async16(bb + soff, &B[(size_t)(bn + row) * K + k0 + lc4]);
        }
        CP_COMMIT();
    };

    prefetch(0);

    for (int s = 0; s < nStages; s++) {
        if (s + 1 < nStages) {
            prefetch(s + 1);
            asm volatile("cp.async.wait_group 1;" ::: "memory");
        } else {
            asm volatile("cp.async.wait_group 0;" ::: "memory");
        }
        __syncthreads();

        const int buf = s & 1;
        const uint32_t* As = (const uint32_t*)(smf + buf * GSTAGE_FLOATS);
        const uint32_t* Bs = As + 128 * GLD;

#pragma unroll
        for (int kk = 0; kk < 4; kk++) {
            uint32_t a[2][4];
#pragma unroll
            for (int mi = 0; mi < 2; mi++) {
                const int r0 = warp_m * 32 + mi * 16 + (lane >> 2);
                const int c0 = kk * 8 + (lane & 3);
                a[mi][0] = As[r0 * GLD + c0];
                a[mi][1] = As[(r0 + 8) * GLD + c0];
                a[mi][2] = As[r0 * GLD + c0 + 4];
                a[mi][3] = As[(r0 + 8) * GLD + c0 + 4];
            }
            uint32_t b[8][2];
#pragma unroll
            for (int ni = 0; ni < 8; ni++) {
                const int n0 = warp_n * 64 + ni * 8 + (lane >> 2);
                const int c0 = kk * 8 + (lane & 3);
                b[ni][0] = Bs[n0 * GLD + c0];
                b[ni][1] = Bs[n0 * GLD + c0 + 4];
            }
#pragma unroll
            for (int mi = 0; mi < 2; mi++)
#pragma unroll
                for (int ni = 0; ni < 8; ni++)
                    mma_tf32(d[mi][ni], a[mi], b[ni]);
        }
        __syncthreads();
    }

#pragma unroll
    for (int mi = 0; mi < 2; mi++) {
        const int row = bm + warp_m * 32 + mi * 16 + (lane >> 2);
#pragma unroll
        for (int ni = 0; ni < 8; ni++) {
            const int col = bn + warp_n * 64 + ni * 8 + ((lane & 3) << 1);
            *(float2*)&C[(size_t)row * N + col] = make_float2(d[mi][ni][0], d[mi][ni][1]);
            *(float2*)&C[(size_t)(row + 8) * N + col] = make_float2(d[mi][ni][2], d[mi][ni][3]);
        }
    }
}

// ---------------------------------------------------------------------------
// RoPE in-place on Q and K laid out [T, H*D].
// ---------------------------------------------------------------------------
__global__ void rope_kernel(float* __restrict__ Q, float* __restrict__ K) {
    const int t = blockIdx.x;
    const float ft = (float)t;
    for (int p = threadIdx.x; p < kH * 64; p += blockDim.x) {
        const int h = p >> 6;
        const int i = p & 63;
        const float inv = __expf(-(float)i * 0.14391157f);
        float s, c;
        sincosf(ft * inv, &s, &c);
        const size_t base = (size_t)t * kC + h * kD;
        {
            float x1 = Q[base + i], x2 = Q[base + 64 + i];
            Q[base + i]      = x1 * c - x2 * s;
            Q[base + 64 + i] = x2 * c + x1 * s;
        }
        {
            float x1 = K[base + i], x2 = K[base + 64 + i];
            K[base + i]      = x1 * c - x2 * s;
            K[base + 64 + i] = x2 * c + x1 * s;
        }
    }
}

// ---------------------------------------------------------------------------
// Tensor-core block-sparse flash attention. One CTA per (q-block, head).
// allowed(kb) = kb <= qb && ((qb-kb) <= 16 || kb < 2 || (kb & 3) == 0)
//
// 256 threads, 8 warps. QK warp tile 16x32 (warp grid 4x2 over 64x64 scores);
// PV warp tile 16x64 (warp grid 4x2 over 64x128 output). K and V both stored
// row-major in a shared KV buffer (B fragments gathered by index — no
// physical transpose, no bank-conflict storms). Softmax is scalar through an
// S->smem round trip; per-row corr / 1/l communicated via smem.
// ---------------------------------------------------------------------------
constexpr int AQLD = 132;   // Q / K / V tiles: [64][132]
constexpr int APLD = 68;    // S/P tile: [64][68]
constexpr int ATTN_SMEM_FLOATS = 64 * AQLD * 2 + 64 * APLD + 64;
constexpr int ATTN_SMEM_BYTES = ATTN_SMEM_FLOATS * 4;   // 85,504 B

__global__ __launch_bounds__(256, 2) void attn_tc(const float* __restrict__ Q,
                                                  const float* __restrict__ K,
                                                  const float* __restrict__ V,
                                                  float* __restrict__ Ctx) {
    extern __shared__ float sm[];
    float* Qs = sm;                      // [64][132]
    float* KV = Qs + 64 * AQLD;          // [64][132]  K then V, row-major
    float* Ps = KV + 64 * AQLD;          // [64][68]   S then P
    float* Cr = Ps + 64 * APLD;          // [64]       corr, then 1/l

    const int qb = blockIdx.x;
    const int h = blockIdx.y;
    const int tid = threadIdx.x;
    const int lane = tid & 31;
    const int wid = tid >> 5;
    const int wm = wid & 3;    // row stripe wm*16
    const int wn = wid >> 2;   // QK: cols wn*32 ; PV: dims wn*64
    const int tr = tid >> 4;   // softmax: rows tr*4..+3
    const int tc = tid & 15;   // softmax: cols tc*4..+3

    const int fr = lane >> 2;  // fragment row within quad group
    const int fc = lane & 3;   // fragment k sub-index

    // Load Q tile, scaled + tf32-rounded
#pragma unroll
    for (int j = 0; j < 8; j++) {
        const int idx = tid * 4 + j * 1024;
        const int rr = idx >> 7;
        const int dd = idx & 127;
        float4 qv = *(const float4*)&Q[(size_t)(qb * 64 + rr) * kC + h * kD + dd];
        qv.x = round_tf32(qv.x * kScale);
        qv.y = round_tf32(qv.y * kScale);
        qv.z = round_tf32(qv.z * kScale);
        qv.w = round_tf32(qv.w * kScale);
        *(float4*)&Qs[rr * AQLD + dd] = qv;
    }

    float m[4], l[4];
#pragma unroll
    for (int i = 0; i < 4; i++) { m[i] = -INFINITY; l[i] = 0.0f; }
    float o[8][4];
#pragma unroll
    for (int ni = 0; ni < 8; ni++)
#pragma unroll
        for (int j = 0; j < 4; j++) o[ni][j] = 0.0f;

    const uint32_t* Qsu = (const uint32_t*)Qs;
    const uint32_t* KVu = (const uint32_t*)KV;
    const uint32_t* Psu = (const uint32_t*)Ps;

    for (int kb = 0; kb <= qb; kb++) {
        const int dist = qb - kb;
        if (!((dist <= 16) || (kb < 2) || ((kb & 3) == 0))) continue;

        __syncthreads();   // prev PV reads of KV / Ps done (also covers Q load)

        // Load K tile row-major, tf32-rounded
#pragma unroll
        for (int j = 0; j < 8; j++) {
            const int idx = tid * 4 + j * 1024;
            const int rr = idx >> 7;
            const int dd = idx & 127;
            float4 kv4 = *(const float4*)&K[(size_t)(kb * 64 + rr) * kC + h * kD + dd];
            kv4.x = round_tf32(kv4.x);
            kv4.y = round_tf32(kv4.y);
            kv4.z = round_tf32(kv4.z);
            kv4.w = round_tf32(kv4.w);
            *(float4*)&KV[rr * AQLD + dd] = kv4;
        }
        __syncthreads();

        // ---- S = Q @ K^T (64x64, K-dim 128 -> 16 mma k-steps) ----
        float s[4][4];
#pragma unroll
        for (int ni = 0; ni < 4; ni++)
#pragma unroll
            for (int j = 0; j < 4; j++) s[ni][j] = 0.0f;

#pragma unroll
        for (int kk = 0; kk < 16; kk++) {
            const int c0 = kk * 8 + fc;
            const int r0 = wm * 16 + fr;
            uint32_t a[4];
            a[0] = Qsu[r0 * AQLD + c0];
            a[1] = Qsu[(r0 + 8) * AQLD + c0];
            a[2] = Qsu[r0 * AQLD + c0 + 4];
            a[3] = Qsu[(r0 + 8) * AQLD + c0 + 4];
#pragma unroll
            for (int ni = 0; ni < 4; ni++) {
                const int n0 = wn * 32 + ni * 8 + fr;
                uint32_t b[2];
                b[0] = KVu[n0 * AQLD + c0];
                b[1] = KVu[n0 * AQLD + c0 + 4];
                mma_tf32(s[ni], a, b);
            }
        }

        // Store S fragments to Ps
#pragma unroll
        for (int ni = 0; ni < 4; ni++) {
            const int r = wm * 16 + fr;
            const int c = wn * 32 + ni * 8 + fc * 2;
            *(float2*)&Ps[r * APLD + c] = make_float2(s[ni][0], s[ni][1]);
            *(float2*)&Ps[(r + 8) * APLD + c] = make_float2(s[ni][2], s[ni][3]);
        }
        __syncthreads();   // S visible; all QK reads of KV done

        // Issue V global loads (latency hidden behind softmax)
        float4 vreg[8];
#pragma unroll
        for (int j = 0; j < 8; j++) {
            const int idx = tid * 4 + j * 1024;
            const int rr = idx >> 7;
            const int dd = idx & 127;
            vreg[j] = *(const float4*)&V[(size_t)(kb * 64 + rr) * kC + h * kD + dd];
        }

        // ---- scalar online softmax (thread owns rows tr*4..+3, cols tc*4..+3) ----
#pragma unroll
        for (int i = 0; i < 4; i++) {
            const int row = tr * 4 + i;
            float4 sv = *(const float4*)&Ps[row * APLD + tc * 4];
            float lm = fmaxf(fmaxf(sv.x, sv.y), fmaxf(sv.z, sv.w));
            lm = fmaxf(lm, __shfl_xor_sync(0xFFFFFFFFu, lm, 1));
            lm = fmaxf(lm, __shfl_xor_sync(0xFFFFFFFFu, lm, 2));
            lm = fmaxf(lm, __shfl_xor_sync(0xFFFFFFFFu, lm, 4));
            lm = fmaxf(lm, __shfl_xor_sync(0xFFFFFFFFu, lm, 8));
            const float mnew = fmaxf(m[i], lm);
            const float corr = __expf(m[i] - mnew);
            float4 p;
            p.x = round_tf32(__expf(sv.x - mnew));
            p.y = round_tf32(__expf(sv.y - mnew));
            p.z = round_tf32(__expf(sv.z - mnew));
            p.w = round_tf32(__expf(sv.w - mnew));
            float rs = (p.x + p.y) + (p.z + p.w);
            rs += __shfl_xor_sync(0xFFFFFFFFu, rs, 1);
            rs += __shfl_xor_sync(0xFFFFFFFFu, rs, 2);
            rs += __shfl_xor_sync(0xFFFFFFFFu, rs, 4);
            rs += __shfl_xor_sync(0xFFFFFFFFu, rs, 8);
            l[i] = l[i] * corr + rs;
            m[i] = mnew;
            *(float4*)&Ps[row * APLD + tc * 4] = p;
            if (tc == 0) Cr[row] = corr;
        }

        // Store V tile row-major, tf32-rounded (KV free since S-store barrier)
#pragma unroll
        for (int j = 0; j < 8; j++) {
            const int idx = tid * 4 + j * 1024;
            const int rr = idx >> 7;
            const int dd = idx & 127;
            float4 v = vreg[j];
            v.x = round_tf32(v.x);
            v.y = round_tf32(v.y);
            v.z = round_tf32(v.z);
            v.w = round_tf32(v.w);
            *(float4*)&KV[rr * AQLD + dd] = v;
        }
        __syncthreads();   // P, corr, V visible

        // ---- O = O*corr + P @ V  (64x128, K-dim 64 -> 8 mma k-steps) ----
        const float c0r = Cr[wm * 16 + fr];
        const float c1r = Cr[wm * 16 + 8 + fr];
#pragma unroll
        for (int ni = 0; ni < 8; ni++) {
            o[ni][0] *= c0r; o[ni][1] *= c0r;
            o[ni][2] *= c1r; o[ni][3] *= c1r;
        }
#pragma unroll
        for (int kk = 0; kk < 8; kk++) {
            const int c0 = kk * 8 + fc;
            const int r0 = wm * 16 + fr;
            uint32_t a[4];
            a[0] = Psu[r0 * APLD + c0];
            a[1] = Psu[(r0 + 8) * APLD + c0];
            a[2] = Psu[r0 * APLD + c0 + 4];
            a[3] = Psu[(r0 + 8) * APLD + c0 + 4];
#pragma unroll
            for (int ni = 0; ni < 8; ni++) {
                const int n0 = wn * 64 + ni * 8 + fr;   // output dim
                uint32_t b[2];
                b[0] = KVu[c0 * AQLD + n0];          // V[k][n]
                b[1] = KVu[(c0 + 4) * AQLD + n0];
                mma_tf32(o[ni], a, b);
            }
        }
    }

    // Publish 1/l, then normalize + round + store
    __syncthreads();
    if (tc == 0) {
#pragma unroll
        for (int i = 0; i < 4; i++) Cr[tr * 4 + i] = 1.0f / l[i];
    }
    __syncthreads();
    const float inv0 = Cr[wm * 16 + fr];
    const float inv1 = Cr[wm * 16 + 8 + fr];
    const int row0 = qb * 64 + wm * 16 + fr;
#pragma unroll
    for (int ni = 0; ni < 8; ni++) {
        const int col = h * kD + wn * 64 + ni * 8 + fc * 2;
        *(float2*)&Ctx[(size_t)row0 * kC + col] =
            make_float2(round_tf32(o[ni][0] * inv0), round_tf32(o[ni][1] * inv0));
        *(float2*)&Ctx[(size_t)(row0 + 8) * kC + col] =
            make_float2(round_tf32(o[ni][2] * inv1), round_tf32(o[ni][3] * inv1));
    }
}

// ---------------------------------------------------------------------------
extern "C" void kernel_launch(void* const* d_in, const int* in_sizes, int n_in,
                              void* d_out, int out_size) {
    const float* x  = (const float*)d_in[0];
    const float* wq = (const float*)d_in[1];
    const float* wk = (const float*)d_in[2];
    const float* wv = (const float*)d_in[3];
    const float* wo = (const float*)d_in[4];
    float* out = (float*)d_out;

    float *qp, *kp, *vp, *cp, *xr, *wr;
    cudaGetSymbolAddress((void**)&qp, g_q);
    cudaGetSymbolAddress((void**)&kp, g_k);
    cudaGetSymbolAddress((void**)&vp, g_v);
    cudaGetSymbolAddress((void**)&cp, g_ctx);
    cudaGetSymbolAddress((void**)&xr, g_xr);
    cudaGetSymbolAddress((void**)&wr, g_wr);

    cudaFuncSetAttribute(gemm_tc, cudaFuncAttributeMaxDynamicSharedMemorySize,
                         GEMM_SMEM_BYTES);
    cudaFuncSetAttribute(attn_tc, cudaFuncAttributeMaxDynamicSharedMemorySize,
                         ATTN_SMEM_BYTES);

    const int CC = kC * kC;
    round_kernel<<<(kT * kC / 4 + 255) / 256, 256>>>(x, xr, kT * kC / 4);
    round_kernel<<<(CC / 4 + 255) / 256, 256>>>(wq, wr + 0 * CC, CC / 4);
    round_kernel<<<(CC / 4 + 255) / 256, 256>>>(wk, wr + 1 * CC, CC / 4);
    round_kernel<<<(CC / 4 + 255) / 256, 256>>>(wv, wr + 2 * CC, CC / 4);
    round_kernel<<<(CC / 4 + 255) / 256, 256>>>(wo, wr + 3 * CC, CC / 4);

    const dim3 ggrid(kC / 128, kT / 128);
    gemm_tc<<<ggrid, 256, GEMM_SMEM_BYTES>>>(xr, wr + 0 * CC, qp, kT, kC, kC);
    gemm_tc<<<ggrid, 256, GEMM_SMEM_BYTES>>>(xr, wr + 1 * CC, kp, kT, kC, kC);
    gemm_tc<<<ggrid, 256, GEMM_SMEM_BYTES>>>(xr, wr + 2 * CC, vp, kT, kC, kC);

    rope_kernel<<<kT, 256>>>(qp, kp);

    attn_tc<<<dim3(kNB, kH), 256, ATTN_SMEM_BYTES>>>(qp, kp, vp, cp);

    gemm_tc<<<ggrid, 256, GEMM_SMEM_BYTES>>>(cp, wr + 3 * CC, out, kT, kC, kC);
}

// round 5
// speedup vs baseline: 7.8765x; 1.0846x over previous
#include <cuda_runtime.h>
#include <math.h>
#include <stdint.h>

// Problem constants
constexpr int kT = 4096;
constexpr int kC = 2048;
constexpr int kH = 16;
constexpr int kD = 128;
constexpr int kNB = 64;
constexpr float kScale = 0.08838834764831845f;

// Scratch (device globals — no cudaMalloc allowed)
__device__ float g_q[kT * kC];
__device__ float g_k[kT * kC];
__device__ float g_v[kT * kC];
__device__ float g_ctx[kT * kC];
__device__ float g_xr[kT * kC];          // tf32-rounded x
__device__ float g_wr[4 * kC * kC];      // tf32-rounded wq,wk,wv,wo

// ---------------------------------------------------------------------------
__device__ __forceinline__ uint32_t smem_u32(const void* p) {
    uint32_t a;
    asm("{ .reg .u64 t; cvta.to.shared.u64 t, %1; cvt.u32.u64 %0, t; }"
        : "=r"(a) : "l"(p));
    return a;
}

__device__ __forceinline__ void cp_async16(uint32_t saddr, const void* gaddr) {
    asm volatile("cp.async.cg.shared.global [%0], [%1], 16;"
                 :: "r"(saddr), "l"(gaddr));
}
#define CP_COMMIT() asm volatile("cp.async.commit_group;" ::: "memory")

__device__ __forceinline__ float round_tf32(float x) {
    uint32_t u;
    asm("cvt.rna.tf32.f32 %0, %1;" : "=r"(u) : "f"(x));
    return __uint_as_float(u);
}

// mma.sync m16n8k8 tf32: D(16x8 f32) += A(16x8) * B(8x8)
__device__ __forceinline__ void mma_tf32(float* d, const uint32_t* a,
                                         const uint32_t* b) {
    asm volatile(
        "mma.sync.aligned.m16n8k8.row.col.f32.tf32.tf32.f32 "
        "{%0,%1,%2,%3}, {%4,%5,%6,%7}, {%8,%9}, {%0,%1,%2,%3};"
        : "+f"(d[0]), "+f"(d[1]), "+f"(d[2]), "+f"(d[3])
        : "r"(a[0]), "r"(a[1]), "r"(a[2]), "r"(a[3]), "r"(b[0]), "r"(b[1]));
}

// ---------------------------------------------------------------------------
// Fused elementwise tf32 rounding: y=0 -> x (2M float4), y in 1..4 -> weights.
// ---------------------------------------------------------------------------
__global__ void round_all(const float* __restrict__ x,
                          const float* __restrict__ wq,
                          const float* __restrict__ wk,
                          const float* __restrict__ wv,
                          const float* __restrict__ wo,
                          float* __restrict__ xr, float* __restrict__ wr) {
    const int y = blockIdx.y;
    const float* src;
    float* dst;
    int n4;
    const int CC = kC * kC;
    if (y == 0) { src = x;  dst = xr;           n4 = kT * kC / 4; }
    else if (y == 1) { src = wq; dst = wr;          n4 = CC / 4; }
    else if (y == 2) { src = wk; dst = wr + CC;     n4 = CC / 4; }
    else if (y == 3) { src = wv; dst = wr + 2 * CC; n4 = CC / 4; }
    else             { src = wo; dst = wr + 3 * CC; n4 = CC / 4; }
    int i = blockIdx.x * blockDim.x + threadIdx.x;
    if (i < n4) {
        float4 v = ((const float4*)src)[i];
        v.x = round_tf32(v.x); v.y = round_tf32(v.y);
        v.z = round_tf32(v.z); v.w = round_tf32(v.w);
        ((float4*)dst)[i] = v;
    }
}

// ---------------------------------------------------------------------------
// TF32 tensor-core GEMM: C[m,n] = sum_k A[m,k] * B[n,k]
// CTA tile 128x128x32, 8 warps (warp tile 32x64).
// 3-stage cp.async pipeline, one __syncthreads per stage.
// Smem rows GLD=32 floats with XOR chunk swizzle (conflict-free, 32KB/stage).
// blockIdx.z selects among up to 3 (B, C) pairs (fused QKV).
// ---------------------------------------------------------------------------
constexpr int GLD = 32;
constexpr int GSTAGE_FLOATS = 2 * 128 * GLD;            // 8192 floats = 32KB
constexpr int GEMM_SMEM_BYTES = 3 * GSTAGE_FLOATS * 4;  // 98304

__device__ __forceinline__ int swoff(int r, int c) {
    // element (row r, col c) within a 128x32 tile, chunk-swizzled
    return r * GLD + ((((c >> 2) ^ (r & 7)) << 2) | (c & 3));
}

__global__ __launch_bounds__(256, 2) void gemm_tc3(
    const float* __restrict__ A,
    const float* __restrict__ B0, const float* __restrict__ B1,
    const float* __restrict__ B2,
    float* __restrict__ C0, float* __restrict__ C1, float* __restrict__ C2,
    int M, int N, int K) {
    const float* B = (blockIdx.z == 0) ? B0 : (blockIdx.z == 1) ? B1 : B2;
    float* C = (blockIdx.z == 0) ? C0 : (blockIdx.z == 1) ? C1 : C2;

    extern __shared__ float smf[];
    const uint32_t sb = smem_u32(smf);
    const int tid = threadIdx.x;
    const int lane = tid & 31;
    const int wid = tid >> 5;
    const int warp_m = wid & 3;
    const int warp_n = wid >> 2;
    const int bm = blockIdx.y * 128;
    const int bn = blockIdx.x * 128;

    const int lrow = tid >> 3;          // 0..31 (+j*32 -> 0..127)
    const int cc8 = tid & 7;            // chunk 0..7

    float d[2][8][4];
#pragma unroll
    for (int mi = 0; mi < 2; mi++)
#pragma unroll
        for (int ni = 0; ni < 8; ni++)
#pragma unroll
            for (int j = 0; j < 4; j++) d[mi][ni][j] = 0.0f;

    const int nStages = K / 32;

    auto prefetch = [&](int s) {
        const int buf = s % 3;
        const uint32_t ab = sb + buf * GSTAGE_FLOATS * 4;
        const uint32_t bb = ab + 128 * GLD * 4;
        const int k0 = s * 32;
#pragma unroll
        for (int j = 0; j < 4; j++) {
            const int row = lrow + j * 32;
            const int scc = cc8 ^ (row & 7);
            const uint32_t soff = (uint32_t)(row * GLD + scc * 4) * 4;
            cp_async16(ab + soff, &A[(size_t)(bm + row) * K + k0 + cc8 * 4]);
            cp_async16(bb + soff, &B[(size_t)(bn + row) * K + k0 + cc8 * 4]);
        }
        CP_COMMIT();
    };

    prefetch(0);
    prefetch(1);

    const int fr = lane >> 2;
    const int fc = lane & 3;

    for (int s = 0; s < nStages; s++) {
        if (s < nStages - 1) {
            asm volatile("cp.async.wait_group 1;" ::: "memory");
        } else {
            asm volatile("cp.async.wait_group 0;" ::: "memory");
        }
        __syncthreads();
        if (s + 2 < nStages) prefetch(s + 2);

        const int buf = s % 3;
        const uint32_t* As = (const uint32_t*)(smf + buf * GSTAGE_FLOATS);
        const uint32_t* Bs = As + 128 * GLD;

#pragma unroll
        for (int kk = 0; kk < 4; kk++) {
            const int c0 = kk * 8 + fc;
            uint32_t a[2][4];
#pragma unroll
            for (int mi = 0; mi < 2; mi++) {
                const int r0 = warp_m * 32 + mi * 16 + fr;
                a[mi][0] = As[swoff(r0, c0)];
                a[mi][1] = As[swoff(r0 + 8, c0)];
                a[mi][2] = As[swoff(r0, c0 + 4)];
                a[mi][3] = As[swoff(r0 + 8, c0 + 4)];
            }
            uint32_t b[8][2];
#pragma unroll
            for (int ni = 0; ni < 8; ni++) {
                const int n0 = warp_n * 64 + ni * 8 + fr;
                b[ni][0] = Bs[swoff(n0, c0)];
                b[ni][1] = Bs[swoff(n0, c0 + 4)];
            }
#pragma unroll
            for (int mi = 0; mi < 2; mi++)
#pragma unroll
                for (int ni = 0; ni < 8; ni++)
                    mma_tf32(d[mi][ni], a[mi], b[ni]);
        }
    }

#pragma unroll
    for (int mi = 0; mi < 2; mi++) {
        const int row = bm + warp_m * 32 + mi * 16 + fr;
#pragma unroll
        for (int ni = 0; ni < 8; ni++) {
            const int col = bn + warp_n * 64 + ni * 8 + fc * 2;
            *(float2*)&C[(size_t)row * N + col] = make_float2(d[mi][ni][0], d[mi][ni][1]);
            *(float2*)&C[(size_t)(row + 8) * N + col] = make_float2(d[mi][ni][2], d[mi][ni][3]);
        }
    }
}

// ---------------------------------------------------------------------------
// RoPE in-place on Q and K laid out [T, H*D].
// ---------------------------------------------------------------------------
__global__ void rope_kernel(float* __restrict__ Q, float* __restrict__ K) {
    const int t = blockIdx.x;
    const float ft = (float)t;
    for (int p = threadIdx.x; p < kH * 64; p += blockDim.x) {
        const int h = p >> 6;
        const int i = p & 63;
        const float inv = __expf(-(float)i * 0.14391157f);
        float s, c;
        sincosf(ft * inv, &s, &c);
        const size_t base = (size_t)t * kC + h * kD;
        {
            float x1 = Q[base + i], x2 = Q[base + 64 + i];
            Q[base + i]      = x1 * c - x2 * s;
            Q[base + 64 + i] = x2 * c + x1 * s;
        }
        {
            float x1 = K[base + i], x2 = K[base + 64 + i];
            K[base + i]      = x1 * c - x2 * s;
            K[base + 64 + i] = x2 * c + x1 * s;
        }
    }
}

// ---------------------------------------------------------------------------
// Tensor-core block-sparse flash attention. One CTA per (q-block, head).
// allowed(kb) = kb <= qb && ((qb-kb) <= 16 || kb < 2 || (kb & 3) == 0)
// (unchanged from round 4 — attention is ~23% of runtime; GEMM is the target)
// ---------------------------------------------------------------------------
constexpr int AQLD = 132;
constexpr int APLD = 68;
constexpr int ATTN_SMEM_FLOATS = 64 * AQLD * 2 + 64 * APLD + 64;
constexpr int ATTN_SMEM_BYTES = ATTN_SMEM_FLOATS * 4;   // 85,504 B

__global__ __launch_bounds__(256, 2) void attn_tc(const float* __restrict__ Q,
                                                  const float* __restrict__ K,
                                                  const float* __restrict__ V,
                                                  float* __restrict__ Ctx) {
    extern __shared__ float sm[];
    float* Qs = sm;                      // [64][132]
    float* KV = Qs + 64 * AQLD;          // [64][132]  K then V, row-major
    float* Ps = KV + 64 * AQLD;          // [64][68]   S then P
    float* Cr = Ps + 64 * APLD;          // [64]       corr, then 1/l

    const int qb = blockIdx.x;
    const int h = blockIdx.y;
    const int tid = threadIdx.x;
    const int lane = tid & 31;
    const int wid = tid >> 5;
    const int wm = wid & 3;
    const int wn = wid >> 2;
    const int tr = tid >> 4;
    const int tc = tid & 15;

    const int fr = lane >> 2;
    const int fc = lane & 3;

#pragma unroll
    for (int j = 0; j < 8; j++) {
        const int idx = tid * 4 + j * 1024;
        const int rr = idx >> 7;
        const int dd = idx & 127;
        float4 qv = *(const float4*)&Q[(size_t)(qb * 64 + rr) * kC + h * kD + dd];
        qv.x = round_tf32(qv.x * kScale);
        qv.y = round_tf32(qv.y * kScale);
        qv.z = round_tf32(qv.z * kScale);
        qv.w = round_tf32(qv.w * kScale);
        *(float4*)&Qs[rr * AQLD + dd] = qv;
    }

    float m[4], l[4];
#pragma unroll
    for (int i = 0; i < 4; i++) { m[i] = -INFINITY; l[i] = 0.0f; }
    float o[8][4];
#pragma unroll
    for (int ni = 0; ni < 8; ni++)
#pragma unroll
        for (int j = 0; j < 4; j++) o[ni][j] = 0.0f;

    const uint32_t* Qsu = (const uint32_t*)Qs;
    const uint32_t* KVu = (const uint32_t*)KV;
    const uint32_t* Psu = (const uint32_t*)Ps;

    for (int kb = 0; kb <= qb; kb++) {
        const int dist = qb - kb;
        if (!((dist <= 16) || (kb < 2) || ((kb & 3) == 0))) continue;

        __syncthreads();

#pragma unroll
        for (int j = 0; j < 8; j++) {
            const int idx = tid * 4 + j * 1024;
            const int rr = idx >> 7;
            const int dd = idx & 127;
            float4 kv4 = *(const float4*)&K[(size_t)(kb * 64 + rr) * kC + h * kD + dd];
            kv4.x = round_tf32(kv4.x);
            kv4.y = round_tf32(kv4.y);
            kv4.z = round_tf32(kv4.z);
            kv4.w = round_tf32(kv4.w);
            *(float4*)&KV[rr * AQLD + dd] = kv4;
        }
        __syncthreads();

        float s[4][4];
#pragma unroll
        for (int ni = 0; ni < 4; ni++)
#pragma unroll
            for (int j = 0; j < 4; j++) s[ni][j] = 0.0f;

#pragma unroll
        for (int kk = 0; kk < 16; kk++) {
            const int c0 = kk * 8 + fc;
            const int r0 = wm * 16 + fr;
            uint32_t a[4];
            a[0] = Qsu[r0 * AQLD + c0];
            a[1] = Qsu[(r0 + 8) * AQLD + c0];
            a[2] = Qsu[r0 * AQLD + c0 + 4];
            a[3] = Qsu[(r0 + 8) * AQLD + c0 + 4];
#pragma unroll
            for (int ni = 0; ni < 4; ni++) {
                const int n0 = wn * 32 + ni * 8 + fr;
                uint32_t b[2];
                b[0] = KVu[n0 * AQLD + c0];
                b[1] = KVu[n0 * AQLD + c0 + 4];
                mma_tf32(s[ni], a, b);
            }
        }

#pragma unroll
        for (int ni = 0; ni < 4; ni++) {
            const int r = wm * 16 + fr;
            const int c = wn * 32 + ni * 8 + fc * 2;
            *(float2*)&Ps[r * APLD + c] = make_float2(s[ni][0], s[ni][1]);
            *(float2*)&Ps[(r + 8) * APLD + c] = make_float2(s[ni][2], s[ni][3]);
        }
        __syncthreads();

        float4 vreg[8];
#pragma unroll
        for (int j = 0; j < 8; j++) {
            const int idx = tid * 4 + j * 1024;
            const int rr = idx >> 7;
            const int dd = idx & 127;
            vreg[j] = *(const float4*)&V[(size_t)(kb * 64 + rr) * kC + h * kD + dd];
        }

#pragma unroll
        for (int i = 0; i < 4; i++) {
            const int row = tr * 4 + i;
            float4 sv = *(const float4*)&Ps[row * APLD + tc * 4];
            float lm = fmaxf(fmaxf(sv.x, sv.y), fmaxf(sv.z, sv.w));
            lm = fmaxf(lm, __shfl_xor_sync(0xFFFFFFFFu, lm, 1));
            lm = fmaxf(lm, __shfl_xor_sync(0xFFFFFFFFu, lm, 2));
            lm = fmaxf(lm, __shfl_xor_sync(0xFFFFFFFFu, lm, 4));
            lm = fmaxf(lm, __shfl_xor_sync(0xFFFFFFFFu, lm, 8));
            const float mnew = fmaxf(m[i], lm);
            const float corr = __expf(m[i] - mnew);
            float4 p;
            p.x = round_tf32(__expf(sv.x - mnew));
            p.y = round_tf32(__expf(sv.y - mnew));
            p.z = round_tf32(__expf(sv.z - mnew));
            p.w = round_tf32(__expf(sv.w - mnew));
            float rs = (p.x + p.y) + (p.z + p.w);
            rs += __shfl_xor_sync(0xFFFFFFFFu, rs, 1);
            rs += __shfl_xor_sync(0xFFFFFFFFu, rs, 2);
            rs += __shfl_xor_sync(0xFFFFFFFFu, rs, 4);
            rs += __shfl_xor_sync(0xFFFFFFFFu, rs, 8);
            l[i] = l[i] * corr + rs;
            m[i] = mnew;
            *(float4*)&Ps[row * APLD + tc * 4] = p;
            if (tc == 0) Cr[row] = corr;
        }

#pragma unroll
        for (int j = 0; j < 8; j++) {
            const int idx = tid * 4 + j * 1024;
            const int rr = idx >> 7;
            const int dd = idx & 127;
            float4 v = vreg[j];
            v.x = round_tf32(v.x);
            v.y = round_tf32(v.y);
            v.z = round_tf32(v.z);
            v.w = round_tf32(v.w);
            *(float4*)&KV[rr * AQLD + dd] = v;
        }
        __syncthreads();

        const float c0r = Cr[wm * 16 + fr];
        const float c1r = Cr[wm * 16 + 8 + fr];
#pragma unroll
        for (int ni = 0; ni < 8; ni++) {
            o[ni][0] *= c0r; o[ni][1] *= c0r;
            o[ni][2] *= c1r; o[ni][3] *= c1r;
        }
#pragma unroll
        for (int kk = 0; kk < 8; kk++) {
            const int c0 = kk * 8 + fc;
            const int r0 = wm * 16 + fr;
            uint32_t a[4];
            a[0] = Psu[r0 * APLD + c0];
            a[1] = Psu[(r0 + 8) * APLD + c0];
            a[2] = Psu[r0 * APLD + c0 + 4];
            a[3] = Psu[(r0 + 8) * APLD + c0 + 4];
#pragma unroll
            for (int ni = 0; ni < 8; ni++) {
                const int n0 = wn * 64 + ni * 8 + fr;
                uint32_t b[2];
                b[0] = KVu[c0 * AQLD + n0];
                b[1] = KVu[(c0 + 4) * AQLD + n0];
                mma_tf32(o[ni], a, b);
            }
        }
    }

    __syncthreads();
    if (tc == 0) {
#pragma unroll
        for (int i = 0; i < 4; i++) Cr[tr * 4 + i] = 1.0f / l[i];
    }
    __syncthreads();
    const float inv0 = Cr[wm * 16 + fr];
    const float inv1 = Cr[wm * 16 + 8 + fr];
    const int row0 = qb * 64 + wm * 16 + fr;
#pragma unroll
    for (int ni = 0; ni < 8; ni++) {
        const int col = h * kD + wn * 64 + ni * 8 + fc * 2;
        *(float2*)&Ctx[(size_t)row0 * kC + col] =
            make_float2(round_tf32(o[ni][0] * inv0), round_tf32(o[ni][1] * inv0));
        *(float2*)&Ctx[(size_t)(row0 + 8) * kC + col] =
            make_float2(round_tf32(o[ni][2] * inv1), round_tf32(o[ni][3] * inv1));
    }
}

// ---------------------------------------------------------------------------
extern "C" void kernel_launch(void* const* d_in, const int* in_sizes, int n_in,
                              void* d_out, int out_size) {
    const float* x  = (const float*)d_in[0];
    const float* wq = (const float*)d_in[1];
    const float* wk = (const float*)d_in[2];
    const float* wv = (const float*)d_in[3];
    const float* wo = (const float*)d_in[4];
    float* out = (float*)d_out;

    float *qp, *kp, *vp, *cp, *xr, *wr;
    cudaGetSymbolAddress((void**)&qp, g_q);
    cudaGetSymbolAddress((void**)&kp, g_k);
    cudaGetSymbolAddress((void**)&vp, g_v);
    cudaGetSymbolAddress((void**)&cp, g_ctx);
    cudaGetSymbolAddress((void**)&xr, g_xr);
    cudaGetSymbolAddress((void**)&wr, g_wr);

    cudaFuncSetAttribute(gemm_tc3, cudaFuncAttributeMaxDynamicSharedMemorySize,
                         GEMM_SMEM_BYTES);
    cudaFuncSetAttribute(attn_tc, cudaFuncAttributeMaxDynamicSharedMemorySize,
                         ATTN_SMEM_BYTES);

    const int CC = kC * kC;

    round_all<<<dim3(kT * kC / 4 / 256, 5), 256>>>(x, wq, wk, wv, wo, xr, wr);

    // Fused QKV projection (blockIdx.z selects weight/output)
    gemm_tc3<<<dim3(kC / 128, kT / 128, 3), 256, GEMM_SMEM_BYTES>>>(
        xr, wr + 0 * CC, wr + 1 * CC, wr + 2 * CC, qp, kp, vp, kT, kC, kC);

    rope_kernel<<<kT, 256>>>(qp, kp);

    attn_tc<<<dim3(kNB, kH), 256, ATTN_SMEM_BYTES>>>(qp, kp, vp, cp);

    // Output projection
    gemm_tc3<<<dim3(kC / 128, kT / 128, 1), 256, GEMM_SMEM_BYTES>>>(
        cp, wr + 3 * CC, wr + 3 * CC, wr + 3 * CC, out, out, out, kT, kC, kC);
}

// round 6
// speedup vs baseline: 8.7831x; 1.1151x over previous
#include <cuda_runtime.h>
#include <math.h>
#include <stdint.h>

// Problem constants
constexpr int kT = 4096;
constexpr int kC = 2048;
constexpr int kH = 16;
constexpr int kD = 128;
constexpr float kScale = 0.08838834764831845f;

// Scratch (device globals — no cudaMalloc allowed)
__device__ float g_q[kT * kC];
__device__ float g_k[kT * kC];
__device__ float g_v[kT * kC];
__device__ float g_ctx[kT * kC];
__device__ float g_xr[kT * kC];          // tf32-rounded x
__device__ float g_wr[4 * kC * kC];      // tf32-rounded wq,wk,wv,wo

// ---------------------------------------------------------------------------
__device__ __forceinline__ uint32_t smem_u32(const void* p) {
    uint32_t a;
    asm("{ .reg .u64 t; cvta.to.shared.u64 t, %1; cvt.u32.u64 %0, t; }"
        : "=r"(a) : "l"(p));
    return a;
}

__device__ __forceinline__ void cp_async16(uint32_t saddr, const void* gaddr) {
    asm volatile("cp.async.cg.shared.global [%0], [%1], 16;"
                 :: "r"(saddr), "l"(gaddr));
}
#define CP_COMMIT() asm volatile("cp.async.commit_group;" ::: "memory")

__device__ __forceinline__ float round_tf32(float x) {
    uint32_t u;
    asm("cvt.rna.tf32.f32 %0, %1;" : "=r"(u) : "f"(x));
    return __uint_as_float(u);
}

// mma.sync m16n8k8 tf32: D(16x8 f32) += A(16x8) * B(8x8)
__device__ __forceinline__ void mma_tf32(float* d, const uint32_t* a,
                                         const uint32_t* b) {
    asm volatile(
        "mma.sync.aligned.m16n8k8.row.col.f32.tf32.tf32.f32 "
        "{%0,%1,%2,%3}, {%4,%5,%6,%7}, {%8,%9}, {%0,%1,%2,%3};"
        : "+f"(d[0]), "+f"(d[1]), "+f"(d[2]), "+f"(d[3])
        : "r"(a[0]), "r"(a[1]), "r"(a[2]), "r"(a[3]), "r"(b[0]), "r"(b[1]));
}

// ---------------------------------------------------------------------------
// Fused elementwise tf32 rounding: y=0 -> x (2M float4), y in 1..4 -> weights.
// ---------------------------------------------------------------------------
__global__ void round_all(const float* __restrict__ x,
                          const float* __restrict__ wq,
                          const float* __restrict__ wk,
                          const float* __restrict__ wv,
                          const float* __restrict__ wo,
                          float* __restrict__ xr, float* __restrict__ wr) {
    const int y = blockIdx.y;
    const float* src;
    float* dst;
    int n4;
    const int CC = kC * kC;
    if (y == 0) { src = x;  dst = xr;           n4 = kT * kC / 4; }
    else if (y == 1) { src = wq; dst = wr;          n4 = CC / 4; }
    else if (y == 2) { src = wk; dst = wr + CC;     n4 = CC / 4; }
    else if (y == 3) { src = wv; dst = wr + 2 * CC; n4 = CC / 4; }
    else             { src = wo; dst = wr + 3 * CC; n4 = CC / 4; }
    int i = blockIdx.x * blockDim.x + threadIdx.x;
    if (i < n4) {
        float4 v = ((const float4*)src)[i];
        v.x = round_tf32(v.x); v.y = round_tf32(v.y);
        v.z = round_tf32(v.z); v.w = round_tf32(v.w);
        ((float4*)dst)[i] = v;
    }
}

// ---------------------------------------------------------------------------
// TF32 tensor-core GEMM: C[m,n] = sum_k A[m,k] * B[n,k]
// CTA tile 128x128x32, 3-stage cp.async pipeline, XOR-swizzled smem.
// blockIdx.z selects among up to 3 (B, C) pairs. roundMask bit z: round output.
// ---------------------------------------------------------------------------
constexpr int GLD = 32;
constexpr int GSTAGE_FLOATS = 2 * 128 * GLD;
constexpr int GEMM_SMEM_BYTES = 3 * GSTAGE_FLOATS * 4;  // 98304

__device__ __forceinline__ int swoff(int r, int c) {
    return r * GLD + ((((c >> 2) ^ (r & 7)) << 2) | (c & 3));
}

__global__ __launch_bounds__(256, 2) void gemm_tc3(
    const float* __restrict__ A,
    const float* __restrict__ B0, const float* __restrict__ B1,
    const float* __restrict__ B2,
    float* __restrict__ C0, float* __restrict__ C1, float* __restrict__ C2,
    int M, int N, int K, unsigned roundMask) {
    const float* B = (blockIdx.z == 0) ? B0 : (blockIdx.z == 1) ? B1 : B2;
    float* C = (blockIdx.z == 0) ? C0 : (blockIdx.z == 1) ? C1 : C2;
    const bool doRound = (roundMask >> blockIdx.z) & 1u;

    extern __shared__ float smf[];
    const uint32_t sb = smem_u32(smf);
    const int tid = threadIdx.x;
    const int lane = tid & 31;
    const int wid = tid >> 5;
    const int warp_m = wid & 3;
    const int warp_n = wid >> 2;
    const int bm = blockIdx.y * 128;
    const int bn = blockIdx.x * 128;

    const int lrow = tid >> 3;
    const int cc8 = tid & 7;

    float d[2][8][4];
#pragma unroll
    for (int mi = 0; mi < 2; mi++)
#pragma unroll
        for (int ni = 0; ni < 8; ni++)
#pragma unroll
            for (int j = 0; j < 4; j++) d[mi][ni][j] = 0.0f;

    const int nStages = K / 32;

    auto prefetch = [&](int s) {
        const int buf = s % 3;
        const uint32_t ab = sb + buf * GSTAGE_FLOATS * 4;
        const uint32_t bb = ab + 128 * GLD * 4;
        const int k0 = s * 32;
#pragma unroll
        for (int j = 0; j < 4; j++) {
            const int row = lrow + j * 32;
            const int scc = cc8 ^ (row & 7);
            const uint32_t soff = (uint32_t)(row * GLD + scc * 4) * 4;
            cp_async16(ab + soff, &A[(size_t)(bm + row) * K + k0 + cc8 * 4]);
            cp_async16(bb + soff, &B[(size_t)(bn + row) * K + k0 + cc8 * 4]);
        }
        CP_COMMIT();
    };

    prefetch(0);
    prefetch(1);

    const int fr = lane >> 2;
    const int fc = lane & 3;

    for (int s = 0; s < nStages; s++) {
        if (s < nStages - 1) {
            asm volatile("cp.async.wait_group 1;" ::: "memory");
        } else {
            asm volatile("cp.async.wait_group 0;" ::: "memory");
        }
        __syncthreads();
        if (s + 2 < nStages) prefetch(s + 2);

        const int buf = s % 3;
        const uint32_t* As = (const uint32_t*)(smf + buf * GSTAGE_FLOATS);
        const uint32_t* Bs = As + 128 * GLD;

#pragma unroll
        for (int kk = 0; kk < 4; kk++) {
            const int c0 = kk * 8 + fc;
            uint32_t a[2][4];
#pragma unroll
            for (int mi = 0; mi < 2; mi++) {
                const int r0 = warp_m * 32 + mi * 16 + fr;
                a[mi][0] = As[swoff(r0, c0)];
                a[mi][1] = As[swoff(r0 + 8, c0)];
                a[mi][2] = As[swoff(r0, c0 + 4)];
                a[mi][3] = As[swoff(r0 + 8, c0 + 4)];
            }
            uint32_t b[8][2];
#pragma unroll
            for (int ni = 0; ni < 8; ni++) {
                const int n0 = warp_n * 64 + ni * 8 + fr;
                b[ni][0] = Bs[swoff(n0, c0)];
                b[ni][1] = Bs[swoff(n0, c0 + 4)];
            }
#pragma unroll
            for (int mi = 0; mi < 2; mi++)
#pragma unroll
                for (int ni = 0; ni < 8; ni++)
                    mma_tf32(d[mi][ni], a[mi], b[ni]);
        }
    }

#pragma unroll
    for (int mi = 0; mi < 2; mi++) {
        const int row = bm + warp_m * 32 + mi * 16 + fr;
#pragma unroll
        for (int ni = 0; ni < 8; ni++) {
            const int col = bn + warp_n * 64 + ni * 8 + fc * 2;
            float2 v0 = make_float2(d[mi][ni][0], d[mi][ni][1]);
            float2 v1 = make_float2(d[mi][ni][2], d[mi][ni][3]);
            if (doRound) {
                v0.x = round_tf32(v0.x); v0.y = round_tf32(v0.y);
                v1.x = round_tf32(v1.x); v1.y = round_tf32(v1.y);
            }
            *(float2*)&C[(size_t)row * N + col] = v0;
            *(float2*)&C[(size_t)(row + 8) * N + col] = v1;
        }
    }
}

// ---------------------------------------------------------------------------
// RoPE in-place on Q and K laid out [T, H*D].
// Q: rotated, scaled by kScale, tf32-rounded. K: rotated, tf32-rounded.
// ---------------------------------------------------------------------------
__global__ void rope_kernel(float* __restrict__ Q, float* __restrict__ K) {
    const int t = blockIdx.x;
    const float ft = (float)t;
    for (int p = threadIdx.x; p < kH * 64; p += blockDim.x) {
        const int h = p >> 6;
        const int i = p & 63;
        const float inv = __expf(-(float)i * 0.14391157f);
        float s, c;
        sincosf(ft * inv, &s, &c);
        const size_t base = (size_t)t * kC + h * kD;
        {
            float x1 = Q[base + i], x2 = Q[base + 64 + i];
            Q[base + i]      = round_tf32((x1 * c - x2 * s) * kScale);
            Q[base + 64 + i] = round_tf32((x2 * c + x1 * s) * kScale);
        }
        {
            float x1 = K[base + i], x2 = K[base + 64 + i];
            K[base + i]      = round_tf32(x1 * c - x2 * s);
            K[base + 64 + i] = round_tf32(x2 * c + x1 * s);
        }
    }
}

// ---------------------------------------------------------------------------
// Tensor-core block-sparse flash attention. One CTA per (q-PAIR, head):
// covers 128 q rows = two 64-token q-blocks. allowed(qb,kb) =
//   kb <= qb && ((qb-kb) <= 16 || kb < 2 || (kb & 3) == 0)
// Per-row masking in softmax handles the two asymmetric diagonal tiles.
// Q/K/V pre-rounded to tf32 upstream; loaded via cp.async.
// 8 warps: QK warp tile 32x32 (grid 4x2 over 128x64 scores);
//          PV warp tile 32x64 (grid 4x2 over 128x128 output).
// ---------------------------------------------------------------------------
constexpr int AQLD = 132;   // Q [128][132], K [64][132]
constexpr int AVLD = 136;   // V [64][136]  (conflict-free PV B-gather)
constexpr int APLD = 68;    // S/P [128][68]
constexpr int ATTN_SMEM_FLOATS =
    128 * AQLD + 64 * AQLD + 64 * AVLD + 128 * APLD + 128;
constexpr int ATTN_SMEM_BYTES = ATTN_SMEM_FLOATS * 4;   // 171,520 B

__global__ __launch_bounds__(256, 1) void attn_tc2(const float* __restrict__ Q,
                                                   const float* __restrict__ K,
                                                   const float* __restrict__ V,
                                                   float* __restrict__ Ctx) {
    extern __shared__ float sm[];
    float* Qs = sm;                         // [128][132]
    float* Ks = Qs + 128 * AQLD;            // [64][132]
    float* Vs = Ks + 64 * AQLD;             // [64][136]
    float* Ps = Vs + 64 * AVLD;             // [128][68]
    float* Cr = Ps + 128 * APLD;            // [128]

    const uint32_t sb = smem_u32(sm);
    const uint32_t QsA = sb;
    const uint32_t KsA = sb + 128 * AQLD * 4;
    const uint32_t VsA = KsA + 64 * AQLD * 4;

    const int qp = blockIdx.x;    // q-pair: rows qp*128..+127
    const int h = blockIdx.y;
    const int q0 = 2 * qp;
    const int q1 = q0 + 1;
    const int tid = threadIdx.x;
    const int lane = tid & 31;
    const int wid = tid >> 5;
    const int wm = wid & 3;       // rows wm*32..+31
    const int wn = wid >> 2;      // QK cols wn*32 ; PV dims wn*64
    const int fr = lane >> 2;
    const int fc = lane & 3;
    const int srow = tid >> 1;    // softmax row 0..127
    const int shalf = tid & 1;    // softmax col half (32 cols each)

    // Q tile via cp.async (pre-scaled + rounded by rope)
#pragma unroll
    for (int j = 0; j < 16; j++) {
        const int idx = tid * 4 + j * 1024;
        const int rr = idx >> 7;
        const int dd = idx & 127;
        cp_async16(QsA + (uint32_t)(rr * AQLD + dd) * 4,
                   &Q[(size_t)(qp * 128 + rr) * kC + h * kD + dd]);
    }
    CP_COMMIT();

    float m = -INFINITY, l = 0.0f;          // per-thread softmax row state
    float o[2][8][4];
#pragma unroll
    for (int mi = 0; mi < 2; mi++)
#pragma unroll
        for (int ni = 0; ni < 8; ni++)
#pragma unroll
            for (int j = 0; j < 4; j++) o[mi][ni][j] = 0.0f;

    const uint32_t* Qsu = (const uint32_t*)Qs;
    const uint32_t* Ksu = (const uint32_t*)Ks;
    const uint32_t* Vsu = (const uint32_t*)Vs;
    const uint32_t* Psu = (const uint32_t*)Ps;

    for (int kb = 0; kb <= q1; kb++) {
        const bool glob = (kb < 2) || ((kb & 3) == 0);
        const bool allowed0 = (kb <= q0) && (((q0 - kb) <= 16) || glob);
        const bool allowed1 = ((q1 - kb) <= 16) || glob;
        if (!allowed0 && !allowed1) continue;

        __syncthreads();   // prev PV reads of Vs/Ps done

        // K + V tiles via cp.async
#pragma unroll
        for (int j = 0; j < 8; j++) {
            const int idx = tid * 4 + j * 1024;
            const int rr = idx >> 7;
            const int dd = idx & 127;
            const size_t gbase = (size_t)(kb * 64 + rr) * kC + h * kD + dd;
            cp_async16(KsA + (uint32_t)(rr * AQLD + dd) * 4, &K[gbase]);
            cp_async16(VsA + (uint32_t)(rr * AVLD + dd) * 4, &V[gbase]);
        }
        CP_COMMIT();
        asm volatile("cp.async.wait_group 0;" ::: "memory");
        __syncthreads();

        // ---- S = Q @ K^T (128x64) ----
        float s[2][4][4];
#pragma unroll
        for (int mi = 0; mi < 2; mi++)
#pragma unroll
            for (int ni = 0; ni < 4; ni++)
#pragma unroll
                for (int j = 0; j < 4; j++) s[mi][ni][j] = 0.0f;

#pragma unroll
        for (int kk = 0; kk < 16; kk++) {
            const int c0 = kk * 8 + fc;
            uint32_t a[2][4];
#pragma unroll
            for (int mi = 0; mi < 2; mi++) {
                const int r0 = wm * 32 + mi * 16 + fr;
                a[mi][0] = Qsu[r0 * AQLD + c0];
                a[mi][1] = Qsu[(r0 + 8) * AQLD + c0];
                a[mi][2] = Qsu[r0 * AQLD + c0 + 4];
                a[mi][3] = Qsu[(r0 + 8) * AQLD + c0 + 4];
            }
            uint32_t b[4][2];
#pragma unroll
            for (int ni = 0; ni < 4; ni++) {
                const int n0 = wn * 32 + ni * 8 + fr;
                b[ni][0] = Ksu[n0 * AQLD + c0];
                b[ni][1] = Ksu[n0 * AQLD + c0 + 4];
            }
#pragma unroll
            for (int mi = 0; mi < 2; mi++)
#pragma unroll
                for (int ni = 0; ni < 4; ni++)
                    mma_tf32(s[mi][ni], a[mi], b[ni]);
        }

        // Store S fragments
#pragma unroll
        for (int mi = 0; mi < 2; mi++) {
            const int r = wm * 32 + mi * 16 + fr;
#pragma unroll
            for (int ni = 0; ni < 4; ni++) {
                const int c = wn * 32 + ni * 8 + fc * 2;
                *(float2*)&Ps[r * APLD + c] = make_float2(s[mi][ni][0], s[mi][ni][1]);
                *(float2*)&Ps[(r + 8) * APLD + c] = make_float2(s[mi][ni][2], s[mi][ni][3]);
            }
        }
        __syncthreads();

        // ---- scalar online softmax: thread owns (row=srow, cols shalf*32..+31) ----
        {
            const bool rowAllowed = (srow < 64) ? allowed0 : allowed1;
            float* prow = &Ps[srow * APLD + shalf * 32];
            if (rowAllowed) {
                float4 sv[8];
#pragma unroll
                for (int j = 0; j < 8; j++) sv[j] = *(const float4*)&prow[j * 4];
                float lm = -INFINITY;
#pragma unroll
                for (int j = 0; j < 8; j++)
                    lm = fmaxf(lm, fmaxf(fmaxf(sv[j].x, sv[j].y), fmaxf(sv[j].z, sv[j].w)));
                lm = fmaxf(lm, __shfl_xor_sync(0xFFFFFFFFu, lm, 1));
                const float mnew = fmaxf(m, lm);
                const float corr = __expf(m - mnew);
                float rs = 0.0f;
#pragma unroll
                for (int j = 0; j < 8; j++) {
                    sv[j].x = round_tf32(__expf(sv[j].x - mnew));
                    sv[j].y = round_tf32(__expf(sv[j].y - mnew));
                    sv[j].z = round_tf32(__expf(sv[j].z - mnew));
                    sv[j].w = round_tf32(__expf(sv[j].w - mnew));
                    rs += (sv[j].x + sv[j].y) + (sv[j].z + sv[j].w);
                    *(float4*)&prow[j * 4] = sv[j];
                }
                rs += __shfl_xor_sync(0xFFFFFFFFu, rs, 1);
                l = l * corr + rs;
                m = mnew;
                if (shalf == 0) Cr[srow] = corr;
            } else {
                const float4 z = make_float4(0.f, 0.f, 0.f, 0.f);
#pragma unroll
                for (int j = 0; j < 8; j++) *(float4*)&prow[j * 4] = z;
                if (shalf == 0) Cr[srow] = 1.0f;
            }
        }
        __syncthreads();

        // ---- O = O*corr + P @ V (128x128) ----
#pragma unroll
        for (int mi = 0; mi < 2; mi++) {
            const float c0r = Cr[wm * 32 + mi * 16 + fr];
            const float c1r = Cr[wm * 32 + mi * 16 + 8 + fr];
#pragma unroll
            for (int ni = 0; ni < 8; ni++) {
                o[mi][ni][0] *= c0r; o[mi][ni][1] *= c0r;
                o[mi][ni][2] *= c1r; o[mi][ni][3] *= c1r;
            }
        }
#pragma unroll
        for (int kk = 0; kk < 8; kk++) {
            const int c0 = kk * 8 + fc;
            uint32_t a[2][4];
#pragma unroll
            for (int mi = 0; mi < 2; mi++) {
                const int r0 = wm * 32 + mi * 16 + fr;
                a[mi][0] = Psu[r0 * APLD + c0];
                a[mi][1] = Psu[(r0 + 8) * APLD + c0];
                a[mi][2] = Psu[r0 * APLD + c0 + 4];
                a[mi][3] = Psu[(r0 + 8) * APLD + c0 + 4];
            }
            uint32_t b[8][2];
#pragma unroll
            for (int ni = 0; ni < 8; ni++) {
                const int n0 = wn * 64 + ni * 8 + fr;
                b[ni][0] = Vsu[c0 * AVLD + n0];
                b[ni][1] = Vsu[(c0 + 4) * AVLD + n0];
            }
#pragma unroll
            for (int mi = 0; mi < 2; mi++)
#pragma unroll
                for (int ni = 0; ni < 8; ni++)
                    mma_tf32(o[mi][ni], a[mi], b[ni]);
        }
    }

    // Publish 1/l, then normalize + round + store
    __syncthreads();
    if (shalf == 0) Cr[srow] = 1.0f / l;
    __syncthreads();
#pragma unroll
    for (int mi = 0; mi < 2; mi++) {
        const float inv0 = Cr[wm * 32 + mi * 16 + fr];
        const float inv1 = Cr[wm * 32 + mi * 16 + 8 + fr];
        const int row0 = qp * 128 + wm * 32 + mi * 16 + fr;
#pragma unroll
        for (int ni = 0; ni < 8; ni++) {
            const int col = h * kD + wn * 64 + ni * 8 + fc * 2;
            *(float2*)&Ctx[(size_t)row0 * kC + col] =
                make_float2(round_tf32(o[mi][ni][0] * inv0),
                            round_tf32(o[mi][ni][1] * inv0));
            *(float2*)&Ctx[(size_t)(row0 + 8) * kC + col] =
                make_float2(round_tf32(o[mi][ni][2] * inv1),
                            round_tf32(o[mi][ni][3] * inv1));
        }
    }
}

// ---------------------------------------------------------------------------
extern "C" void kernel_launch(void* const* d_in, const int* in_sizes, int n_in,
                              void* d_out, int out_size) {
    const float* x  = (const float*)d_in[0];
    const float* wq = (const float*)d_in[1];
    const float* wk = (const float*)d_in[2];
    const float* wv = (const float*)d_in[3];
    const float* wo = (const float*)d_in[4];
    float* out = (float*)d_out;

    float *qp, *kp, *vp, *cp, *xr, *wr;
    cudaGetSymbolAddress((void**)&qp, g_q);
    cudaGetSymbolAddress((void**)&kp, g_k);
    cudaGetSymbolAddress((void**)&vp, g_v);
    cudaGetSymbolAddress((void**)&cp, g_ctx);
    cudaGetSymbolAddress((void**)&xr, g_xr);
    cudaGetSymbolAddress((void**)&wr, g_wr);

    cudaFuncSetAttribute(gemm_tc3, cudaFuncAttributeMaxDynamicSharedMemorySize,
                         GEMM_SMEM_BYTES);
    cudaFuncSetAttribute(attn_tc2, cudaFuncAttributeMaxDynamicSharedMemorySize,
                         ATTN_SMEM_BYTES);

    const int CC = kC * kC;

    round_all<<<dim3(kT * kC / 4 / 256, 5), 256>>>(x, wq, wk, wv, wo, xr, wr);

    // Fused QKV projection; V output tf32-rounded in epilogue (mask bit 2)
    gemm_tc3<<<dim3(kC / 128, kT / 128, 3), 256, GEMM_SMEM_BYTES>>>(
        xr, wr + 0 * CC, wr + 1 * CC, wr + 2 * CC, qp, kp, vp, kT, kC, kC, 4u);

    rope_kernel<<<kT, 256>>>(qp, kp);

    attn_tc2<<<dim3(kT / 128, kH), 256, ATTN_SMEM_BYTES>>>(qp, kp, vp, cp);

    // Output projection (no rounding)
    gemm_tc3<<<dim3(kC / 128, kT / 128, 1), 256, GEMM_SMEM_BYTES>>>(
        cp, wr + 3 * CC, wr + 3 * CC, wr + 3 * CC, out, out, out, kT, kC, kC, 0u);
}

// round 7
// speedup vs baseline: 9.1852x; 1.0458x over previous
#include <cuda_runtime.h>
#include <math.h>
#include <stdint.h>

// Problem constants
constexpr int kT = 4096;
constexpr int kC = 2048;
constexpr int kH = 16;
constexpr int kD = 128;
constexpr float kScale = 0.08838834764831845f;

// Scratch (device globals — no cudaMalloc allowed)
__device__ float g_q[kT * kC];
__device__ float g_k[kT * kC];
__device__ float g_v[kT * kC];
__device__ float g_ctx[kT * kC];
__device__ float g_xr[kT * kC];          // tf32-rounded x
__device__ float g_wr[4 * kC * kC];      // tf32-rounded wq,wk,wv,wo

// ---------------------------------------------------------------------------
__device__ __forceinline__ uint32_t smem_u32(const void* p) {
    uint32_t a;
    asm("{ .reg .u64 t; cvta.to.shared.u64 t, %1; cvt.u32.u64 %0, t; }"
        : "=r"(a) : "l"(p));
    return a;
}

__device__ __forceinline__ void cp_async16(uint32_t saddr, const void* gaddr) {
    asm volatile("cp.async.cg.shared.global [%0], [%1], 16;"
                 :: "r"(saddr), "l"(gaddr));
}
#define CP_COMMIT() asm volatile("cp.async.commit_group;" ::: "memory")

__device__ __forceinline__ float round_tf32(float x) {
    uint32_t u;
    asm("cvt.rna.tf32.f32 %0, %1;" : "=r"(u) : "f"(x));
    return __uint_as_float(u);
}

// mma.sync m16n8k8 tf32: D(16x8 f32) += A(16x8) * B(8x8)
__device__ __forceinline__ void mma_tf32(float* d, const uint32_t* a,
                                         const uint32_t* b) {
    asm volatile(
        "mma.sync.aligned.m16n8k8.row.col.f32.tf32.tf32.f32 "
        "{%0,%1,%2,%3}, {%4,%5,%6,%7}, {%8,%9}, {%0,%1,%2,%3};"
        : "+f"(d[0]), "+f"(d[1]), "+f"(d[2]), "+f"(d[3])
        : "r"(a[0]), "r"(a[1]), "r"(a[2]), "r"(a[3]), "r"(b[0]), "r"(b[1]));
}

// ---------------------------------------------------------------------------
// Fused elementwise tf32 rounding: y=0 -> x, y in 1..4 -> weights.
// ---------------------------------------------------------------------------
__global__ void round_all(const float* __restrict__ x,
                          const float* __restrict__ wq,
                          const float* __restrict__ wk,
                          const float* __restrict__ wv,
                          const float* __restrict__ wo,
                          float* __restrict__ xr, float* __restrict__ wr) {
    const int y = blockIdx.y;
    const float* src;
    float* dst;
    int n4;
    const int CC = kC * kC;
    if (y == 0) { src = x;  dst = xr;           n4 = kT * kC / 4; }
    else if (y == 1) { src = wq; dst = wr;          n4 = CC / 4; }
    else if (y == 2) { src = wk; dst = wr + CC;     n4 = CC / 4; }
    else if (y == 3) { src = wv; dst = wr + 2 * CC; n4 = CC / 4; }
    else             { src = wo; dst = wr + 3 * CC; n4 = CC / 4; }
    int i = blockIdx.x * blockDim.x + threadIdx.x;
    if (i < n4) {
        float4 v = ((const float4*)src)[i];
        v.x = round_tf32(v.x); v.y = round_tf32(v.y);
        v.z = round_tf32(v.z); v.w = round_tf32(v.w);
        ((float4*)dst)[i] = v;
    }
}

// ---------------------------------------------------------------------------
// TF32 tensor-core GEMM: C[m,n] = sum_k A[m,k] * B[n,k]
// CTA tile 128x128x32, 3-stage cp.async pipeline, XOR-swizzled smem.
// blockIdx.z selects among up to 3 (B, C) pairs. roundMask bit z: round output.
// ---------------------------------------------------------------------------
constexpr int GLD = 32;
constexpr int GSTAGE_FLOATS = 2 * 128 * GLD;
constexpr int GEMM_SMEM_BYTES = 3 * GSTAGE_FLOATS * 4;  // 98304

__device__ __forceinline__ int swoff(int r, int c) {
    return r * GLD + ((((c >> 2) ^ (r & 7)) << 2) | (c & 3));
}

__global__ __launch_bounds__(256, 2) void gemm_tc3(
    const float* __restrict__ A,
    const float* __restrict__ B0, const float* __restrict__ B1,
    const float* __restrict__ B2,
    float* __restrict__ C0, float* __restrict__ C1, float* __restrict__ C2,
    int M, int N, int K, unsigned roundMask) {
    const float* B = (blockIdx.z == 0) ? B0 : (blockIdx.z == 1) ? B1 : B2;
    float* C = (blockIdx.z == 0) ? C0 : (blockIdx.z == 1) ? C1 : C2;
    const bool doRound = (roundMask >> blockIdx.z) & 1u;

    extern __shared__ float smf[];
    const uint32_t sb = smem_u32(smf);
    const int tid = threadIdx.x;
    const int lane = tid & 31;
    const int wid = tid >> 5;
    const int warp_m = wid & 3;
    const int warp_n = wid >> 2;
    const int bm = blockIdx.y * 128;
    const int bn = blockIdx.x * 128;

    const int lrow = tid >> 3;
    const int cc8 = tid & 7;

    float d[2][8][4];
#pragma unroll
    for (int mi = 0; mi < 2; mi++)
#pragma unroll
        for (int ni = 0; ni < 8; ni++)
#pragma unroll
            for (int j = 0; j < 4; j++) d[mi][ni][j] = 0.0f;

    const int nStages = K / 32;

    auto prefetch = [&](int s) {
        const int buf = s % 3;
        const uint32_t ab = sb + buf * GSTAGE_FLOATS * 4;
        const uint32_t bb = ab + 128 * GLD * 4;
        const int k0 = s * 32;
#pragma unroll
        for (int j = 0; j < 4; j++) {
            const int row = lrow + j * 32;
            const int scc = cc8 ^ (row & 7);
            const uint32_t soff = (uint32_t)(row * GLD + scc * 4) * 4;
            cp_async16(ab + soff, &A[(size_t)(bm + row) * K + k0 + cc8 * 4]);
            cp_async16(bb + soff, &B[(size_t)(bn + row) * K + k0 + cc8 * 4]);
        }
        CP_COMMIT();
    };

    prefetch(0);
    prefetch(1);

    const int fr = lane >> 2;
    const int fc = lane & 3;

    for (int s = 0; s < nStages; s++) {
        if (s < nStages - 1) {
            asm volatile("cp.async.wait_group 1;" ::: "memory");
        } else {
            asm volatile("cp.async.wait_group 0;" ::: "memory");
        }
        __syncthreads();
        if (s + 2 < nStages) prefetch(s + 2);

        const int buf = s % 3;
        const uint32_t* As = (const uint32_t*)(smf + buf * GSTAGE_FLOATS);
        const uint32_t* Bs = As + 128 * GLD;

#pragma unroll
        for (int kk = 0; kk < 4; kk++) {
            const int c0 = kk * 8 + fc;
            uint32_t a[2][4];
#pragma unroll
            for (int mi = 0; mi < 2; mi++) {
                const int r0 = warp_m * 32 + mi * 16 + fr;
                a[mi][0] = As[swoff(r0, c0)];
                a[mi][1] = As[swoff(r0 + 8, c0)];
                a[mi][2] = As[swoff(r0, c0 + 4)];
                a[mi][3] = As[swoff(r0 + 8, c0 + 4)];
            }
            uint32_t b[8][2];
#pragma unroll
            for (int ni = 0; ni < 8; ni++) {
                const int n0 = warp_n * 64 + ni * 8 + fr;
                b[ni][0] = Bs[swoff(n0, c0)];
                b[ni][1] = Bs[swoff(n0, c0 + 4)];
            }
#pragma unroll
            for (int mi = 0; mi < 2; mi++)
#pragma unroll
                for (int ni = 0; ni < 8; ni++)
                    mma_tf32(d[mi][ni], a[mi], b[ni]);
        }
    }

#pragma unroll
    for (int mi = 0; mi < 2; mi++) {
        const int row = bm + warp_m * 32 + mi * 16 + fr;
#pragma unroll
        for (int ni = 0; ni < 8; ni++) {
            const int col = bn + warp_n * 64 + ni * 8 + fc * 2;
            float2 v0 = make_float2(d[mi][ni][0], d[mi][ni][1]);
            float2 v1 = make_float2(d[mi][ni][2], d[mi][ni][3]);
            if (doRound) {
                v0.x = round_tf32(v0.x); v0.y = round_tf32(v0.y);
                v1.x = round_tf32(v1.x); v1.y = round_tf32(v1.y);
            }
            *(float2*)&C[(size_t)row * N + col] = v0;
            *(float2*)&C[(size_t)(row + 8) * N + col] = v1;
        }
    }
}

// ---------------------------------------------------------------------------
// RoPE in-place on Q and K laid out [T, H*D].
// Q: rotated, scaled by kScale, tf32-rounded. K: rotated, tf32-rounded.
// ---------------------------------------------------------------------------
__global__ void rope_kernel(float* __restrict__ Q, float* __restrict__ K) {
    const int t = blockIdx.x;
    const float ft = (float)t;
    for (int p = threadIdx.x; p < kH * 64; p += blockDim.x) {
        const int h = p >> 6;
        const int i = p & 63;
        const float inv = __expf(-(float)i * 0.14391157f);
        float s, c;
        sincosf(ft * inv, &s, &c);
        const size_t base = (size_t)t * kC + h * kD;
        {
            float x1 = Q[base + i], x2 = Q[base + 64 + i];
            Q[base + i]      = round_tf32((x1 * c - x2 * s) * kScale);
            Q[base + 64 + i] = round_tf32((x2 * c + x1 * s) * kScale);
        }
        {
            float x1 = K[base + i], x2 = K[base + 64 + i];
            K[base + i]      = round_tf32(x1 * c - x2 * s);
            K[base + 64 + i] = round_tf32(x2 * c + x1 * s);
        }
    }
}

// ---------------------------------------------------------------------------
// Tensor-core block-sparse flash attention. One CTA per (q-PAIR, head):
// covers 128 q rows. Software-pipelined cp.async: K(i+1) issued after QK(i),
// V(i+1) issued after PV(i) — loads hidden behind compute, no extra smem.
// Heavy CTAs (high qp) launched first for tail packing.
// ---------------------------------------------------------------------------
constexpr int AQLD = 132;   // Q [128][132], K [64][132]
constexpr int AVLD = 136;   // V [64][136]
constexpr int APLD = 68;    // S/P [128][68]
constexpr int ATTN_SMEM_FLOATS =
    128 * AQLD + 64 * AQLD + 64 * AVLD + 128 * APLD + 128;
constexpr int ATTN_SMEM_BYTES = ATTN_SMEM_FLOATS * 4;   // 171,520 B

__global__ __launch_bounds__(256, 1) void attn_tc2(const float* __restrict__ Q,
                                                   const float* __restrict__ K,
                                                   const float* __restrict__ V,
                                                   float* __restrict__ Ctx) {
    extern __shared__ float sm[];
    float* Qs = sm;                         // [128][132]
    float* Ks = Qs + 128 * AQLD;            // [64][132]
    float* Vs = Ks + 64 * AQLD;             // [64][136]
    float* Ps = Vs + 64 * AVLD;             // [128][68]
    float* Cr = Ps + 128 * APLD;            // [128]

    const uint32_t sb = smem_u32(sm);
    const uint32_t QsA = sb;
    const uint32_t KsA = sb + 128 * AQLD * 4;
    const uint32_t VsA = KsA + 64 * AQLD * 4;

    const int qp = (gridDim.x - 1) - blockIdx.x;   // heavy-first
    const int h = blockIdx.y;
    const int q0 = 2 * qp;
    const int q1 = q0 + 1;
    const int tid = threadIdx.x;
    const int lane = tid & 31;
    const int wid = tid >> 5;
    const int wm = wid & 3;
    const int wn = wid >> 2;
    const int fr = lane >> 2;
    const int fc = lane & 3;
    const int srow = tid >> 1;
    const int shalf = tid & 1;

    auto is_allowed = [&](int t) {
        const bool glob = (t < 2) || ((t & 3) == 0);
        const bool a0 = (t <= q0) && (((q0 - t) <= 16) || glob);
        const bool a1 = ((q1 - t) <= 16) || glob;
        return a0 || a1;
    };

    auto issueK = [&](int t) {
#pragma unroll
        for (int j = 0; j < 8; j++) {
            const int idx = tid * 4 + j * 1024;
            const int rr = idx >> 7;
            const int dd = idx & 127;
            cp_async16(KsA + (uint32_t)(rr * AQLD + dd) * 4,
                       &K[(size_t)(t * 64 + rr) * kC + h * kD + dd]);
        }
        CP_COMMIT();
    };
    auto issueV = [&](int t) {
#pragma unroll
        for (int j = 0; j < 8; j++) {
            const int idx = tid * 4 + j * 1024;
            const int rr = idx >> 7;
            const int dd = idx & 127;
            cp_async16(VsA + (uint32_t)(rr * AVLD + dd) * 4,
                       &V[(size_t)(t * 64 + rr) * kC + h * kD + dd]);
        }
        CP_COMMIT();
    };

    // Q tile (group 0), then K0 (group 1), V0 (group 2)
#pragma unroll
    for (int j = 0; j < 16; j++) {
        const int idx = tid * 4 + j * 1024;
        const int rr = idx >> 7;
        const int dd = idx & 127;
        cp_async16(QsA + (uint32_t)(rr * AQLD + dd) * 4,
                   &Q[(size_t)(qp * 128 + rr) * kC + h * kD + dd]);
    }
    CP_COMMIT();
    int kb = 0;                 // kb=0 is always allowed
    issueK(kb);
    issueV(kb);

    float m = -INFINITY, l = 0.0f;
    float o[2][8][4];
#pragma unroll
    for (int mi = 0; mi < 2; mi++)
#pragma unroll
        for (int ni = 0; ni < 8; ni++)
#pragma unroll
            for (int j = 0; j < 4; j++) o[mi][ni][j] = 0.0f;

    const uint32_t* Qsu = (const uint32_t*)Qs;
    const uint32_t* Ksu = (const uint32_t*)Ks;
    const uint32_t* Vsu = (const uint32_t*)Vs;
    const uint32_t* Psu = (const uint32_t*)Ps;

    while (true) {
        // next allowed tile (or kb itself on the last tile)
        int kbn = kb;
        for (int t = kb + 1; t <= q1; t++) {
            if (is_allowed(t)) { kbn = t; break; }
        }
        const bool glob = (kb < 2) || ((kb & 3) == 0);
        const bool allowed0 = (kb <= q0) && (((q0 - kb) <= 16) || glob);
        const bool allowed1 = ((q1 - kb) <= 16) || glob;

        // wait for K(kb) (Q on first iter too); V(kb) may still be in flight
        asm volatile("cp.async.wait_group 1;" ::: "memory");
        __syncthreads();

        // ---- S = Q @ K^T (128x64) ----
        float s[2][4][4];
#pragma unroll
        for (int mi = 0; mi < 2; mi++)
#pragma unroll
            for (int ni = 0; ni < 4; ni++)
#pragma unroll
                for (int j = 0; j < 4; j++) s[mi][ni][j] = 0.0f;

#pragma unroll
        for (int kk = 0; kk < 16; kk++) {
            const int c0 = kk * 8 + fc;
            uint32_t a[2][4];
#pragma unroll
            for (int mi = 0; mi < 2; mi++) {
                const int r0 = wm * 32 + mi * 16 + fr;
                a[mi][0] = Qsu[r0 * AQLD + c0];
                a[mi][1] = Qsu[(r0 + 8) * AQLD + c0];
                a[mi][2] = Qsu[r0 * AQLD + c0 + 4];
                a[mi][3] = Qsu[(r0 + 8) * AQLD + c0 + 4];
            }
            uint32_t b[4][2];
#pragma unroll
            for (int ni = 0; ni < 4; ni++) {
                const int n0 = wn * 32 + ni * 8 + fr;
                b[ni][0] = Ksu[n0 * AQLD + c0];
                b[ni][1] = Ksu[n0 * AQLD + c0 + 4];
            }
#pragma unroll
            for (int mi = 0; mi < 2; mi++)
#pragma unroll
                for (int ni = 0; ni < 4; ni++)
                    mma_tf32(s[mi][ni], a[mi], b[ni]);
        }

        // Store S fragments
#pragma unroll
        for (int mi = 0; mi < 2; mi++) {
            const int r = wm * 32 + mi * 16 + fr;
#pragma unroll
            for (int ni = 0; ni < 4; ni++) {
                const int c = wn * 32 + ni * 8 + fc * 2;
                *(float2*)&Ps[r * APLD + c] = make_float2(s[mi][ni][0], s[mi][ni][1]);
                *(float2*)&Ps[(r + 8) * APLD + c] = make_float2(s[mi][ni][2], s[mi][ni][3]);
            }
        }
        __syncthreads();   // all QK reads of Ks done; S visible

        // prefetch next K into the (now free) K buffer — overlaps softmax+PV
        issueK(kbn);

        // ---- scalar online softmax (row srow, cols shalf*32..+31) ----
        {
            const bool rowAllowed = (srow < 64) ? allowed0 : allowed1;
            float* prow = &Ps[srow * APLD + shalf * 32];
            if (rowAllowed) {
                float4 sv[8];
#pragma unroll
                for (int j = 0; j < 8; j++) sv[j] = *(const float4*)&prow[j * 4];
                float lm = -INFINITY;
#pragma unroll
                for (int j = 0; j < 8; j++)
                    lm = fmaxf(lm, fmaxf(fmaxf(sv[j].x, sv[j].y), fmaxf(sv[j].z, sv[j].w)));
                lm = fmaxf(lm, __shfl_xor_sync(0xFFFFFFFFu, lm, 1));
                const float mnew = fmaxf(m, lm);
                const float corr = __expf(m - mnew);
                float rs = 0.0f;
#pragma unroll
                for (int j = 0; j < 8; j++) {
                    sv[j].x = round_tf32(__expf(sv[j].x - mnew));
                    sv[j].y = round_tf32(__expf(sv[j].y - mnew));
                    sv[j].z = round_tf32(__expf(sv[j].z - mnew));
                    sv[j].w = round_tf32(__expf(sv[j].w - mnew));
                    rs += (sv[j].x + sv[j].y) + (sv[j].z + sv[j].w);
                    *(float4*)&prow[j * 4] = sv[j];
                }
                rs += __shfl_xor_sync(0xFFFFFFFFu, rs, 1);
                l = l * corr + rs;
                m = mnew;
                if (shalf == 0) Cr[srow] = corr;
            } else {
                const float4 z = make_float4(0.f, 0.f, 0.f, 0.f);
#pragma unroll
                for (int j = 0; j < 8; j++) *(float4*)&prow[j * 4] = z;
                if (shalf == 0) Cr[srow] = 1.0f;
            }
        }

        // wait for V(kb) (K(kbn) stays in flight), then sync publishes P/Cr/V
        asm volatile("cp.async.wait_group 1;" ::: "memory");
        __syncthreads();

        // ---- O = O*corr + P @ V (128x128) ----
#pragma unroll
        for (int mi = 0; mi < 2; mi++) {
            const float c0r = Cr[wm * 32 + mi * 16 + fr];
            const float c1r = Cr[wm * 32 + mi * 16 + 8 + fr];
#pragma unroll
            for (int ni = 0; ni < 8; ni++) {
                o[mi][ni][0] *= c0r; o[mi][ni][1] *= c0r;
                o[mi][ni][2] *= c1r; o[mi][ni][3] *= c1r;
            }
        }
#pragma unroll
        for (int kk = 0; kk < 8; kk++) {
            const int c0 = kk * 8 + fc;
            uint32_t a[2][4];
#pragma unroll
            for (int mi = 0; mi < 2; mi++) {
                const int r0 = wm * 32 + mi * 16 + fr;
                a[mi][0] = Psu[r0 * APLD + c0];
                a[mi][1] = Psu[(r0 + 8) * APLD + c0];
                a[mi][2] = Psu[r0 * APLD + c0 + 4];
                a[mi][3] = Psu[(r0 + 8) * APLD + c0 + 4];
            }
            uint32_t b[8][2];
#pragma unroll
            for (int ni = 0; ni < 8; ni++) {
                const int n0 = wn * 64 + ni * 8 + fr;
                b[ni][0] = Vsu[c0 * AVLD + n0];
                b[ni][1] = Vsu[(c0 + 4) * AVLD + n0];
            }
#pragma unroll
            for (int mi = 0; mi < 2; mi++)
#pragma unroll
                for (int ni = 0; ni < 8; ni++)
                    mma_tf32(o[mi][ni], a[mi], b[ni]);
        }
        __syncthreads();   // PV reads of Vs/Ps done

        // prefetch next V — overlaps next tile's QK+softmax
        issueV(kbn);

        if (kbn == kb) break;
        kb = kbn;
    }

    // Drain outstanding dummy prefetches, publish 1/l, store
    asm volatile("cp.async.wait_group 0;" ::: "memory");
    __syncthreads();
    if (shalf == 0) Cr[srow] = 1.0f / l;
    __syncthreads();
#pragma unroll
    for (int mi = 0; mi < 2; mi++) {
        const float inv0 = Cr[wm * 32 + mi * 16 + fr];
        const float inv1 = Cr[wm * 32 + mi * 16 + 8 + fr];
        const int row0 = qp * 128 + wm * 32 + mi * 16 + fr;
#pragma unroll
        for (int ni = 0; ni < 8; ni++) {
            const int col = h * kD + wn * 64 + ni * 8 + fc * 2;
            *(float2*)&Ctx[(size_t)row0 * kC + col] =
                make_float2(round_tf32(o[mi][ni][0] * inv0),
                            round_tf32(o[mi][ni][1] * inv0));
            *(float2*)&Ctx[(size_t)(row0 + 8) * kC + col] =
                make_float2(round_tf32(o[mi][ni][2] * inv1),
                            round_tf32(o[mi][ni][3] * inv1));
        }
    }
}

// ---------------------------------------------------------------------------
extern "C" void kernel_launch(void* const* d_in, const int* in_sizes, int n_in,
                              void* d_out, int out_size) {
    const float* x  = (const float*)d_in[0];
    const float* wq = (const float*)d_in[1];
    const float* wk = (const float*)d_in[2];
    const float* wv = (const float*)d_in[3];
    const float* wo = (const float*)d_in[4];
    float* out = (float*)d_out;

    float *qp, *kp, *vp, *cp, *xr, *wr;
    cudaGetSymbolAddress((void**)&qp, g_q);
    cudaGetSymbolAddress((void**)&kp, g_k);
    cudaGetSymbolAddress((void**)&vp, g_v);
    cudaGetSymbolAddress((void**)&cp, g_ctx);
    cudaGetSymbolAddress((void**)&xr, g_xr);
    cudaGetSymbolAddress((void**)&wr, g_wr);

    cudaFuncSetAttribute(gemm_tc3, cudaFuncAttributeMaxDynamicSharedMemorySize,
                         GEMM_SMEM_BYTES);
    cudaFuncSetAttribute(attn_tc2, cudaFuncAttributeMaxDynamicSharedMemorySize,
                         ATTN_SMEM_BYTES);

    const int CC = kC * kC;

    round_all<<<dim3(kT * kC / 4 / 256, 5), 256>>>(x, wq, wk, wv, wo, xr, wr);

    // Fused QKV projection; V output tf32-rounded in epilogue (mask bit 2)
    gemm_tc3<<<dim3(kC / 128, kT / 128, 3), 256, GEMM_SMEM_BYTES>>>(
        xr, wr + 0 * CC, wr + 1 * CC, wr + 2 * CC, qp, kp, vp, kT, kC, kC, 4u);

    rope_kernel<<<kT, 256>>>(qp, kp);

    attn_tc2<<<dim3(kT / 128, kH), 256, ATTN_SMEM_BYTES>>>(qp, kp, vp, cp);

    // Output projection (no rounding)
    gemm_tc3<<<dim3(kC / 128, kT / 128, 1), 256, GEMM_SMEM_BYTES>>>(
        cp, wr + 3 * CC, wr + 3 * CC, wr + 3 * CC, out, out, out, kT, kC, kC, 0u);
}